// round 13
// baseline (speedup 1.0000x reference)
#include <cuda_runtime.h>
#include <cuda_bf16.h>
#include <math.h>
#include <stdint.h>

typedef __nv_bfloat16 bf16;
typedef __nv_bfloat162 bf162;

// Problem constants
#define BATCH 4
#define SEQ   4096
#define DIM   1024
#define MTOT  (BATCH * SEQ)     // 16384
#define HALF_D (DIM / 2)        // 512

// GEMM tiling: 128x128 CTA tile, 4 warps of 64x64
#define BM 128
#define BN 128
#define BK 32
#define GTH 128                         // gemm block threads (4 warps)
#define NTHREADS 256                    // helper-kernel block size
#define SKB 40                          // padded smem row stride (bf16) = 80 B
#define BUFB (BM * SKB)                 // 5120 bf16 per operand buffer
#define SMEM_BYTES (2 * 4 * BUFB * 2)   // 2 stages x 4 operands x bf16 = 81920 B
#define VSTRIDE 133                     // fp32 stage buffer column stride (conflict-free)

// -------- device scratch (no cudaMalloc allowed) --------
__device__ bf16 g_xhi[(size_t)MTOT * DIM];
__device__ bf16 g_xlo[(size_t)MTOT * DIM];
__device__ bf16 g_Whi[(size_t)3 * DIM * DIM];
__device__ bf16 g_Wlo[(size_t)3 * DIM * DIM];
__device__ bf16 g_Qhi[(size_t)MTOT * DIM];
__device__ bf16 g_Qlo[(size_t)MTOT * DIM];
__device__ bf16 g_Khi[(size_t)MTOT * DIM];
__device__ bf16 g_Klo[(size_t)MTOT * DIM];
__device__ bf16 g_Vthi[(size_t)MTOT * DIM];   // [b][dim][seq]
__device__ bf16 g_Vtlo[(size_t)MTOT * DIM];
__device__ bf16 g_Pbh[(size_t)BATCH * SEQ * SEQ];   // unnormalized exp(scores), split
__device__ bf16 g_Pbl[(size_t)BATCH * SEQ * SEQ];
__device__ float g_rsum[(size_t)MTOT];              // per-row sum of exp
__device__ float g_cos[(size_t)SEQ * HALF_D];
__device__ float g_sin[(size_t)SEQ * HALF_D];

// ============================================================
// helpers
// ============================================================
__device__ __forceinline__ void split_bf16(float x, bf16& hi, bf16& lo) {
    hi = __float2bfloat16_rn(x);
    lo = __float2bfloat16_rn(x - __bfloat162float(hi));
}

#define MMA_BF16(D, A, B)                                                   \
    asm volatile(                                                           \
        "mma.sync.aligned.m16n8k16.row.col.f32.bf16.bf16.f32 "              \
        "{%0,%1,%2,%3}, {%4,%5,%6,%7}, {%8,%9}, {%0,%1,%2,%3};"             \
        : "+f"((D)[0]), "+f"((D)[1]), "+f"((D)[2]), "+f"((D)[3])            \
        : "r"((A)[0]), "r"((A)[1]), "r"((A)[2]), "r"((A)[3]),               \
          "r"((B)[0]), "r"((B)[1]))

#define LDSM_X4(R, addr)                                                    \
    asm volatile(                                                           \
        "ldmatrix.sync.aligned.m8n8.x4.shared.b16 {%0,%1,%2,%3}, [%4];"     \
        : "=r"((R)[0]), "=r"((R)[1]), "=r"((R)[2]), "=r"((R)[3])            \
        : "r"(addr))

#define CP_ASYNC16(dst, src)                                                \
    asm volatile("cp.async.cg.shared.global [%0], [%1], 16;"                \
                 :: "r"(dst), "l"(src))
#define CP_COMMIT() asm volatile("cp.async.commit_group;")
#define CP_WAIT0()  asm volatile("cp.async.wait_group 0;")

// ============================================================
// RoPE cos/sin table (double precision generation)
// ============================================================
__global__ void trig_table_kernel(float* ct, float* st) {
    int idx = blockIdx.x * blockDim.x + threadIdx.x;
    if (idx >= SEQ * HALF_D) return;
    int s = idx / HALF_D;
    int j = idx % HALF_D;
    double inv = exp(-((double)(2 * j) / (double)DIM) * 9.210340371976184);
    double ang = (double)s * inv;
    double sv, cv;
    sincos(ang, &sv, &cv);
    ct[idx] = (float)cv;
    st[idx] = (float)sv;
}

// ============================================================
// Split fp32 array into bf16 hi/lo
// ============================================================
__global__ void split_kernel(const float* __restrict__ src,
                             bf16* __restrict__ hi, bf16* __restrict__ lo,
                             int n) {
    int i = blockIdx.x * blockDim.x + threadIdx.x;
    if (i >= n) return;
    bf16 h, l;
    split_bf16(src[i], h, l);
    hi[i] = h;
    lo[i] = l;
}

// Split all three weight matrices in one launch
__global__ void split_w3_kernel(const float* __restrict__ Wq,
                                const float* __restrict__ Wk,
                                const float* __restrict__ Wv,
                                bf16* __restrict__ hi, bf16* __restrict__ lo) {
    const int nw = DIM * DIM;
    int i = blockIdx.x * blockDim.x + threadIdx.x;
    if (i >= 3 * nw) return;
    const float* src = (i < nw) ? Wq : (i < 2 * nw) ? Wk : Wv;
    float v = src[i >= 2 * nw ? i - 2 * nw : (i >= nw ? i - nw : i)];
    bf16 h, l;
    split_bf16(v, h, l);
    hi[i] = h;
    lo[i] = l;
}

// ============================================================
// 3xBF16 GEMM core, 4 warps x (64x64) warp tiles.
// acc[mt][nt][4]: mt 0..3 (m16), nt 0..7 (n8).
// Term-major MMA ordering: consecutive MMAs hit distinct
// accumulators (RAW distance 32) to keep the tensor pipe fed.
// ============================================================
__device__ __forceinline__ void gemm3_core(
    const bf16* __restrict__ Ahi, const bf16* __restrict__ Alo, int lda,
    const bf16* __restrict__ Bhi, const bf16* __restrict__ Blo, int ldb,
    int m0, int n0, int kSteps, float acc[4][8][4]) {
    extern __shared__ bf16 smem[];
    const int tid = threadIdx.x;
    const int wid = tid >> 5;          // 0..3
    const int lane = tid & 31;
    const int wm = (wid & 1) * 64;
    const int wn = (wid >> 1) * 64;

    // ldmatrix per-lane addressing
    const uint32_t a_row  = lane & 15;
    const uint32_t a_koff = (uint32_t)((lane >> 4) << 3);          // 0 or 8 elems
    const uint32_t b_row  = (uint32_t)((lane & 7) + ((lane >> 4) << 3));
    const uint32_t b_koff = (uint32_t)(((lane >> 3) & 1) << 3);    // 0 or 8 elems

    uint32_t smem_u32 = (uint32_t)__cvta_generic_to_shared(smem);

#pragma unroll
    for (int mt = 0; mt < 4; mt++)
#pragma unroll
        for (int nt = 0; nt < 8; nt++)
#pragma unroll
            for (int c = 0; c < 4; c++) acc[mt][nt][c] = 0.0f;

    const bf16* srcs[4];
    srcs[0] = Ahi + (size_t)m0 * lda;
    srcs[1] = Alo + (size_t)m0 * lda;
    srcs[2] = Bhi + (size_t)n0 * ldb;
    srcs[3] = Blo + (size_t)n0 * ldb;
    int ldsz[4] = {lda, lda, ldb, ldb};

    auto load_chunk = [&](int stage, int k0) {
#pragma unroll
        for (int i = 0; i < 16; i++) {
            const int op = i >> 2;
            const int q = tid + GTH * (i & 3);       // 0..511 per operand
            const int r = q >> 2;                    // row 0..127
            const int c = (q & 3) * 8;               // bf16 col 0,8,16,24
            uint32_t dst = smem_u32 +
                (uint32_t)(((stage * 4 + op) * BUFB + r * SKB + c) * 2);
            const bf16* src = srcs[op] + (size_t)r * ldsz[op] + k0 + c;
            CP_ASYNC16(dst, src);
        }
        CP_COMMIT();
    };

    // prologue
    load_chunk(0, 0);
    CP_WAIT0();
    __syncthreads();

    for (int it = 0; it < kSteps; it++) {
        int s = it & 1;
        if (it + 1 < kSteps) load_chunk((it + 1) & 1, (it + 1) * BK);

        const uint32_t stA_h = smem_u32 + (uint32_t)((s * 4 + 0) * BUFB * 2);
        const uint32_t stA_l = smem_u32 + (uint32_t)((s * 4 + 1) * BUFB * 2);
        const uint32_t stB_h = smem_u32 + (uint32_t)((s * 4 + 2) * BUFB * 2);
        const uint32_t stB_l = smem_u32 + (uint32_t)((s * 4 + 3) * BUFB * 2);

#pragma unroll
        for (int kc = 0; kc < 2; kc++) {          // two k16 chunks per BK=32
            const uint32_t kbase = (uint32_t)(kc * 16);
            uint32_t ah[4][4], al[4][4], bh[8][2], bl[8][2];
#pragma unroll
            for (int mt = 0; mt < 4; mt++) {
                uint32_t ra = (uint32_t)(((wm + mt * 16 + a_row) * SKB + kbase + a_koff) * 2);
                LDSM_X4(ah[mt], stA_h + ra);
                LDSM_X4(al[mt], stA_l + ra);
            }
#pragma unroll
            for (int p = 0; p < 4; p++) {         // nt pairs (2p, 2p+1)
                uint32_t rb = (uint32_t)(((wn + p * 16 + b_row) * SKB + kbase + b_koff) * 2);
                uint32_t t[4];
                LDSM_X4(t, stB_h + rb);
                bh[2 * p][0] = t[0]; bh[2 * p][1] = t[1];
                bh[2 * p + 1][0] = t[2]; bh[2 * p + 1][1] = t[3];
                LDSM_X4(t, stB_l + rb);
                bl[2 * p][0] = t[0]; bl[2 * p][1] = t[1];
                bl[2 * p + 1][0] = t[2]; bl[2 * p + 1][1] = t[3];
            }
            // term-major: no two consecutive MMAs share an accumulator
#pragma unroll
            for (int mt = 0; mt < 4; mt++)
#pragma unroll
                for (int nt = 0; nt < 8; nt++)
                    MMA_BF16(acc[mt][nt], ah[mt], bh[nt]);
#pragma unroll
            for (int mt = 0; mt < 4; mt++)
#pragma unroll
                for (int nt = 0; nt < 8; nt++)
                    MMA_BF16(acc[mt][nt], ah[mt], bl[nt]);
#pragma unroll
            for (int mt = 0; mt < 4; mt++)
#pragma unroll
                for (int nt = 0; nt < 8; nt++)
                    MMA_BF16(acc[mt][nt], al[mt], bh[nt]);
        }
        if (it + 1 < kSteps) CP_WAIT0();
        __syncthreads();
    }
}

// ============================================================
// Combined QKV projection. grid = (DIM/BN, MTOT/BM, 3)
// z=0: Q (rope+split), z=1: K (rope+split), z=2: V (smem-staged
// transposed coalesced split store)
// ============================================================
__global__ __launch_bounds__(GTH, 2)
void qkv_mma_kernel(const bf16* __restrict__ Ahi, const bf16* __restrict__ Alo,
                    const bf16* __restrict__ Whi, const bf16* __restrict__ Wlo,
                    bf16* __restrict__ Qh, bf16* __restrict__ Ql,
                    bf16* __restrict__ Kh, bf16* __restrict__ Kl,
                    bf16* __restrict__ Vth, bf16* __restrict__ Vtl,
                    const float* __restrict__ Ct, const float* __restrict__ St) {
    const int n0 = blockIdx.x * BN;
    const int m0 = blockIdx.y * BM;
    const int z  = blockIdx.z;
    const size_t nw = (size_t)DIM * DIM;

    float acc[4][8][4];
    gemm3_core(Ahi, Alo, DIM, Whi + z * nw, Wlo + z * nw, DIM, m0, n0, DIM / BK, acc);

    const int tid = threadIdx.x;
    const int wid = tid >> 5;
    const int lane = tid & 31;
    const int grp = lane >> 2;
    const int tig = lane & 3;
    const int wm = (wid & 1) * 64;
    const int wn = (wid >> 1) * 64;

    if (z != 2) {
        bf16* Ohi = (z == 0) ? Qh : Kh;
        bf16* Olo = (z == 0) ? Ql : Kl;
#pragma unroll
        for (int mt = 0; mt < 4; mt++)
#pragma unroll
            for (int nt = 0; nt < 8; nt++)
#pragma unroll
                for (int h = 0; h < 2; h++) {
                    int row = m0 + wm + mt * 16 + grp + 8 * h;
                    int colE = n0 + wn + nt * 8 + tig * 2;
                    float e = acc[mt][nt][2 * h];
                    float o = acc[mt][nt][2 * h + 1];
                    int s = row & (SEQ - 1);
                    int j = colE >> 1;
                    float cth = Ct[(size_t)s * HALF_D + j];
                    float sth = St[(size_t)s * HALF_D + j];
                    float re = e * cth - o * sth;
                    float ro = e * sth + o * cth;
                    bf16 h1, l1, h2, l2;
                    split_bf16(re, h1, l1);
                    split_bf16(ro, h2, l2);
                    size_t p = (size_t)row * DIM + colE;
                    *(bf162*)(Ohi + p) = bf162{h1, h2};
                    *(bf162*)(Olo + p) = bf162{l1, l2};
                }
    } else {
        // ---- V: stage fp32 tile in smem as [col][row], then coalesced
        //      transposed split stores (16B chunks along seq). ----
        extern __shared__ bf16 smem[];
        float* vbuf = (float*)smem;   // 128 cols x VSTRIDE floats = 68.1 KB <= 80 KB
        // mainloop ended with __syncthreads(); smem free to reuse
#pragma unroll
        for (int mt = 0; mt < 4; mt++)
#pragma unroll
            for (int nt = 0; nt < 8; nt++)
#pragma unroll
                for (int h = 0; h < 2; h++) {
                    int rowL = wm + mt * 16 + grp + 8 * h;
                    int colL = wn + nt * 8 + tig * 2;
                    vbuf[colL * VSTRIDE + rowL]       = acc[mt][nt][2 * h];
                    vbuf[(colL + 1) * VSTRIDE + rowL] = acc[mt][nt][2 * h + 1];
                }
        __syncthreads();

        const int bq = m0 >> 12;          // batch (tiles never straddle)
        const int sbase = m0 & (SEQ - 1);
        const int col = tid;               // 0..127
        const float* srcc = vbuf + col * VSTRIDE;
        size_t gbase = ((size_t)bq * DIM + n0 + col) * SEQ + sbase;
#pragma unroll
        for (int j0 = 0; j0 < 128; j0 += 8) {
            bf16 h8[8], l8[8];
#pragma unroll
            for (int j = 0; j < 8; j++) split_bf16(srcc[j0 + j], h8[j], l8[j]);
            *(uint4*)(Vth + gbase + j0) = *(uint4*)h8;
            *(uint4*)(Vtl + gbase + j0) = *(uint4*)l8;
        }
    }
}

// ============================================================
// Scores+exp: E = exp((Q K^T)/32) masked causal, split bf16 output.
// (No row-max: scores are O(few), exp cannot overflow fp32; softmax
//  is shift-invariant so normalization by the row-sum suffices.)
// grid = (SEQ/BN, SEQ/BM, BATCH)
// ============================================================
__global__ __launch_bounds__(GTH, 2)
void scores_mma_kernel(const bf16* __restrict__ Qhi, const bf16* __restrict__ Qlo,
                       const bf16* __restrict__ Khi, const bf16* __restrict__ Klo,
                       bf16* __restrict__ Pbh, bf16* __restrict__ Pbl) {
    const int n0 = blockIdx.x * BN;
    const int m0 = blockIdx.y * BM;
    if (n0 > m0) return;
    const int b = blockIdx.z;
    const size_t boff = (size_t)b * SEQ * DIM;

    float acc[4][8][4];
    gemm3_core(Qhi + boff, Qlo + boff, DIM, Khi + boff, Klo + boff, DIM,
               m0, n0, DIM / BK, acc);

    const int tid = threadIdx.x;
    const int wid = tid >> 5;
    const int lane = tid & 31;
    const int grp = lane >> 2;
    const int tig = lane & 3;
    const int wm = (wid & 1) * 64;
    const int wn = (wid >> 1) * 64;
    const float scale = 1.0f / 32.0f;

    bf16* Ph = Pbh + (size_t)b * SEQ * SEQ;
    bf16* Pl = Pbl + (size_t)b * SEQ * SEQ;
#pragma unroll
    for (int mt = 0; mt < 4; mt++)
#pragma unroll
        for (int nt = 0; nt < 8; nt++)
#pragma unroll
            for (int h = 0; h < 2; h++) {
                int row = m0 + wm + mt * 16 + grp + 8 * h;
                int col = n0 + wn + nt * 8 + tig * 2;
                float e0 = (col     <= row) ? __expf(acc[mt][nt][2 * h]     * scale) : 0.0f;
                float e1 = (col + 1 <= row) ? __expf(acc[mt][nt][2 * h + 1] * scale) : 0.0f;
                bf16 h0, l0, h1, l1;
                split_bf16(e0, h0, l0);
                split_bf16(e1, h1, l1);
                size_t p = (size_t)row * SEQ + col;
                *(bf162*)(Ph + p) = bf162{h0, h1};
                *(bf162*)(Pl + p) = bf162{l0, l1};
            }
}

// ============================================================
// Deterministic per-row sum of split exp values. Block per row.
// ============================================================
__global__ __launch_bounds__(NTHREADS)
void rowsum_kernel(const bf16* __restrict__ Pbh, const bf16* __restrict__ Pbl,
                   float* __restrict__ rsum) {
    __shared__ float red[NTHREADS / 32];
    const int rowg = blockIdx.x;
    const int b = rowg >> 12;
    const int i = rowg & (SEQ - 1);
    const bf16* ph = Pbh + ((size_t)b * SEQ + i) * SEQ;
    const bf16* pl = Pbl + ((size_t)b * SEQ + i) * SEQ;
    const int bound = (i & ~127) + 128;   // masked zeros cover (i, bound)
    const int tid = threadIdx.x;
    const int lane = tid & 31;
    const int wrp = tid >> 5;

    float sum = 0.0f;
    for (int j = tid * 2; j < bound; j += NTHREADS * 2) {
        bf162 h2 = *(const bf162*)(ph + j);
        bf162 l2 = *(const bf162*)(pl + j);
        sum += __bfloat162float(h2.x) + __bfloat162float(l2.x);
        sum += __bfloat162float(h2.y) + __bfloat162float(l2.y);
    }
#pragma unroll
    for (int o = 16; o > 0; o >>= 1) sum += __shfl_xor_sync(~0u, sum, o);
    if (lane == 0) red[wrp] = sum;
    __syncthreads();
    if (tid == 0) {
        float s = 0.0f;
#pragma unroll
        for (int w = 0; w < NTHREADS / 32; w++) s += red[w];
        rsum[rowg] = s;
    }
}

// ============================================================
// PV: O = (E @ V) / rowsum using Vt (K-major), causal-truncated k-loop.
// grid = (DIM/BN, SEQ/BM, BATCH); m-tiles reversed so heavy tiles go first.
// ============================================================
__global__ __launch_bounds__(GTH, 2)
void pv_mma_kernel(const bf16* __restrict__ Pbh, const bf16* __restrict__ Pbl,
                   const bf16* __restrict__ Vthi, const bf16* __restrict__ Vtlo,
                   const float* __restrict__ rsum, float* __restrict__ O) {
    const int n0 = blockIdx.x * BN;
    const int m0 = (int)(gridDim.y - 1 - blockIdx.y) * BM;   // heavy first
    const int b = blockIdx.z;

    const bf16* Ah = Pbh + (size_t)b * SEQ * SEQ;
    const bf16* Al = Pbl + (size_t)b * SEQ * SEQ;
    const bf16* Bh = Vthi + (size_t)b * DIM * SEQ;
    const bf16* Bl = Vtlo + (size_t)b * DIM * SEQ;

    float acc[4][8][4];
    gemm3_core(Ah, Al, SEQ, Bh, Bl, SEQ, m0, n0, (m0 + BM) / BK, acc);

    const int tid = threadIdx.x;
    const int wid = tid >> 5;
    const int lane = tid & 31;
    const int grp = lane >> 2;
    const int tig = lane & 3;
    const int wm = (wid & 1) * 64;
    const int wn = (wid >> 1) * 64;

#pragma unroll
    for (int mt = 0; mt < 4; mt++)
#pragma unroll
        for (int nt = 0; nt < 8; nt++)
#pragma unroll
            for (int h = 0; h < 2; h++) {
                int row = m0 + wm + mt * 16 + grp + 8 * h;
                int col = n0 + wn + nt * 8 + tig * 2;
                float inv = 1.0f / rsum[(size_t)b * SEQ + row];
                float2 v;
                v.x = acc[mt][nt][2 * h] * inv;
                v.y = acc[mt][nt][2 * h + 1] * inv;
                *(float2*)(O + ((size_t)b * SEQ + row) * DIM + col) = v;
            }
}

// ============================================================
// Launch
// ============================================================
extern "C" void kernel_launch(void* const* d_in, const int* in_sizes, int n_in,
                              void* d_out, int out_size) {
    const float* x  = (const float*)d_in[0];
    const float* Wq = (const float*)d_in[1];
    const float* Wk = (const float*)d_in[2];
    const float* Wv = (const float*)d_in[3];
    float* out = (float*)d_out;

    bf16 *xh, *xl, *Wh, *Wl, *Qh, *Ql, *Kh, *Kl, *Vth, *Vtl, *Pbh, *Pbl;
    float *Rs, *Cp, *Sp;
    cudaGetSymbolAddress((void**)&xh, g_xhi);
    cudaGetSymbolAddress((void**)&xl, g_xlo);
    cudaGetSymbolAddress((void**)&Wh, g_Whi);
    cudaGetSymbolAddress((void**)&Wl, g_Wlo);
    cudaGetSymbolAddress((void**)&Qh, g_Qhi);
    cudaGetSymbolAddress((void**)&Ql, g_Qlo);
    cudaGetSymbolAddress((void**)&Kh, g_Khi);
    cudaGetSymbolAddress((void**)&Kl, g_Klo);
    cudaGetSymbolAddress((void**)&Vth, g_Vthi);
    cudaGetSymbolAddress((void**)&Vtl, g_Vtlo);
    cudaGetSymbolAddress((void**)&Pbh, g_Pbh);
    cudaGetSymbolAddress((void**)&Pbl, g_Pbl);
    cudaGetSymbolAddress((void**)&Rs, g_rsum);
    cudaGetSymbolAddress((void**)&Cp, g_cos);
    cudaGetSymbolAddress((void**)&Sp, g_sin);

    cudaFuncSetAttribute(qkv_mma_kernel,    cudaFuncAttributeMaxDynamicSharedMemorySize, SMEM_BYTES);
    cudaFuncSetAttribute(scores_mma_kernel, cudaFuncAttributeMaxDynamicSharedMemorySize, SMEM_BYTES);
    cudaFuncSetAttribute(pv_mma_kernel,     cudaFuncAttributeMaxDynamicSharedMemorySize, SMEM_BYTES);

    // 1) trig tables
    {
        int total = SEQ * HALF_D;
        trig_table_kernel<<<(total + 255) / 256, 256>>>(Cp, Sp);
    }
    // 2) split x
    {
        int nx = MTOT * DIM;
        split_kernel<<<(nx + 255) / 256, 256>>>(x, xh, xl, nx);
    }
    // 3) split all weights (one launch)
    {
        int n3 = 3 * DIM * DIM;
        split_w3_kernel<<<(n3 + 255) / 256, 256>>>(Wq, Wk, Wv, Wh, Wl);
    }

    // 4) QKV projections (single launch, grid.z selects Q/K/V)
    {
        dim3 grid(DIM / BN, MTOT / BM, 3);   // (8, 128, 3)
        qkv_mma_kernel<<<grid, GTH, SMEM_BYTES>>>(xh, xl, Wh, Wl,
                                                  Qh, Ql, Kh, Kl, Vth, Vtl,
                                                  Cp, Sp);
    }
    // 5) scores + exp + causal mask (split output, no softmax pass)
    {
        dim3 grid(SEQ / BN, SEQ / BM, BATCH);
        scores_mma_kernel<<<grid, GTH, SMEM_BYTES>>>(Qh, Ql, Kh, Kl, Pbh, Pbl);
    }
    // 6) deterministic row sums
    rowsum_kernel<<<BATCH * SEQ, NTHREADS>>>(Pbh, Pbl, Rs);

    // 7) O = (E @ V) / rowsum
    {
        dim3 grid(DIM / BN, SEQ / BM, BATCH);
        pv_mma_kernel<<<grid, GTH, SMEM_BYTES>>>(Pbh, Pbl, Vth, Vtl, Rs, out);
    }
}

// round 14
// speedup vs baseline: 1.1178x; 1.1178x over previous
#include <cuda_runtime.h>
#include <cuda_bf16.h>
#include <cuda_fp16.h>
#include <math.h>
#include <stdint.h>

typedef __nv_bfloat16 bf16;
typedef __nv_bfloat162 bf162;
typedef __half f16;
typedef __half2 f162;

// Problem constants
#define BATCH 4
#define SEQ   4096
#define DIM   1024
#define MTOT  (BATCH * SEQ)     // 16384
#define HALF_D (DIM / 2)        // 512

// GEMM tiling: 128x128 CTA tile, 4 warps of 64x64
#define BM 128
#define BN 128
#define BK 32
#define GTH 128                         // gemm block threads (4 warps)
#define NTHREADS 256                    // helper-kernel block size
#define SKB 40                          // padded smem row stride (16-bit elems) = 80 B
#define BUFB (BM * SKB)                 // 5120 elems per operand buffer
#define SMEM_BYTES (2 * 4 * BUFB * 2)   // 2 stages x 4 operands = 81920 B
#define VSTRIDE 133                     // fp32 stage buffer column stride (conflict-free)

// -------- device scratch (no cudaMalloc allowed) --------
__device__ bf16 g_xhi[(size_t)MTOT * DIM];
__device__ bf16 g_xlo[(size_t)MTOT * DIM];
__device__ bf16 g_Whi[(size_t)3 * DIM * DIM];
__device__ bf16 g_Wlo[(size_t)3 * DIM * DIM];
__device__ bf16 g_Qhi[(size_t)MTOT * DIM];
__device__ bf16 g_Qlo[(size_t)MTOT * DIM];
__device__ bf16 g_Khi[(size_t)MTOT * DIM];
__device__ bf16 g_Klo[(size_t)MTOT * DIM];
__device__ f16  g_Vth[(size_t)MTOT * DIM];    // fp16 split V^T [b][dim][seq]
__device__ f16  g_Vtl[(size_t)MTOT * DIM];
__device__ f16  g_Pf[(size_t)BATCH * SEQ * SEQ];    // unnormalized exp(scores), fp16
__device__ float g_rsum[(size_t)MTOT];              // per-row sum of exp
__device__ float g_cos[(size_t)SEQ * HALF_D];
__device__ float g_sin[(size_t)SEQ * HALF_D];

// ============================================================
// helpers
// ============================================================
__device__ __forceinline__ void split_bf16(float x, bf16& hi, bf16& lo) {
    hi = __float2bfloat16_rn(x);
    lo = __float2bfloat16_rn(x - __bfloat162float(hi));
}
__device__ __forceinline__ void split_f16(float x, f16& hi, f16& lo) {
    hi = __float2half_rn(x);
    lo = __float2half_rn(x - __half2float(hi));
}

#define MMA_BF16(D, A, B)                                                   \
    asm volatile(                                                           \
        "mma.sync.aligned.m16n8k16.row.col.f32.bf16.bf16.f32 "              \
        "{%0,%1,%2,%3}, {%4,%5,%6,%7}, {%8,%9}, {%0,%1,%2,%3};"             \
        : "+f"((D)[0]), "+f"((D)[1]), "+f"((D)[2]), "+f"((D)[3])            \
        : "r"((A)[0]), "r"((A)[1]), "r"((A)[2]), "r"((A)[3]),               \
          "r"((B)[0]), "r"((B)[1]))

#define MMA_F16(D, A, B)                                                    \
    asm volatile(                                                           \
        "mma.sync.aligned.m16n8k16.row.col.f32.f16.f16.f32 "                \
        "{%0,%1,%2,%3}, {%4,%5,%6,%7}, {%8,%9}, {%0,%1,%2,%3};"             \
        : "+f"((D)[0]), "+f"((D)[1]), "+f"((D)[2]), "+f"((D)[3])            \
        : "r"((A)[0]), "r"((A)[1]), "r"((A)[2]), "r"((A)[3]),               \
          "r"((B)[0]), "r"((B)[1]))

#define LDSM_X4(R, addr)                                                    \
    asm volatile(                                                           \
        "ldmatrix.sync.aligned.m8n8.x4.shared.b16 {%0,%1,%2,%3}, [%4];"     \
        : "=r"((R)[0]), "=r"((R)[1]), "=r"((R)[2]), "=r"((R)[3])            \
        : "r"(addr))

#define CP_ASYNC16(dst, src)                                                \
    asm volatile("cp.async.cg.shared.global [%0], [%1], 16;"                \
                 :: "r"(dst), "l"(src))
#define CP_COMMIT() asm volatile("cp.async.commit_group;")
#define CP_WAIT0()  asm volatile("cp.async.wait_group 0;")

// ============================================================
// RoPE cos/sin table (double precision generation)
// ============================================================
__global__ void trig_table_kernel(float* ct, float* st) {
    int idx = blockIdx.x * blockDim.x + threadIdx.x;
    if (idx >= SEQ * HALF_D) return;
    int s = idx / HALF_D;
    int j = idx % HALF_D;
    double inv = exp(-((double)(2 * j) / (double)DIM) * 9.210340371976184);
    double ang = (double)s * inv;
    double sv, cv;
    sincos(ang, &sv, &cv);
    ct[idx] = (float)cv;
    st[idx] = (float)sv;
}

// ============================================================
// Split fp32 array into bf16 hi/lo
// ============================================================
__global__ void split_kernel(const float* __restrict__ src,
                             bf16* __restrict__ hi, bf16* __restrict__ lo,
                             int n) {
    int i = blockIdx.x * blockDim.x + threadIdx.x;
    if (i >= n) return;
    bf16 h, l;
    split_bf16(src[i], h, l);
    hi[i] = h;
    lo[i] = l;
}

// Split all three weight matrices in one launch
__global__ void split_w3_kernel(const float* __restrict__ Wq,
                                const float* __restrict__ Wk,
                                const float* __restrict__ Wv,
                                bf16* __restrict__ hi, bf16* __restrict__ lo) {
    const int nw = DIM * DIM;
    int i = blockIdx.x * blockDim.x + threadIdx.x;
    if (i >= 3 * nw) return;
    const float* src = (i < nw) ? Wq : (i < 2 * nw) ? Wk : Wv;
    float v = src[i >= 2 * nw ? i - 2 * nw : (i >= nw ? i - nw : i)];
    bf16 h, l;
    split_bf16(v, h, l);
    hi[i] = h;
    lo[i] = l;
}

// ============================================================
// 3xBF16 GEMM core, 4 warps x (64x64) warp tiles.
// cp.async prefetch issued AFTER kc0 fragment LDSMs so fragment
// loads are not queued behind the prefetch on the LSU pipe.
// ============================================================
__device__ __forceinline__ void gemm3_core(
    const bf16* __restrict__ Ahi, const bf16* __restrict__ Alo, int lda,
    const bf16* __restrict__ Bhi, const bf16* __restrict__ Blo, int ldb,
    int m0, int n0, int kSteps, float acc[4][8][4]) {
    extern __shared__ bf16 smem[];
    const int tid = threadIdx.x;
    const int wid = tid >> 5;          // 0..3
    const int lane = tid & 31;
    const int wm = (wid & 1) * 64;
    const int wn = (wid >> 1) * 64;

    const uint32_t a_row  = lane & 15;
    const uint32_t a_koff = (uint32_t)((lane >> 4) << 3);
    const uint32_t b_row  = (uint32_t)((lane & 7) + ((lane >> 4) << 3));
    const uint32_t b_koff = (uint32_t)(((lane >> 3) & 1) << 3);

    uint32_t smem_u32 = (uint32_t)__cvta_generic_to_shared(smem);

#pragma unroll
    for (int mt = 0; mt < 4; mt++)
#pragma unroll
        for (int nt = 0; nt < 8; nt++)
#pragma unroll
            for (int c = 0; c < 4; c++) acc[mt][nt][c] = 0.0f;

    const bf16* srcs[4];
    srcs[0] = Ahi + (size_t)m0 * lda;
    srcs[1] = Alo + (size_t)m0 * lda;
    srcs[2] = Bhi + (size_t)n0 * ldb;
    srcs[3] = Blo + (size_t)n0 * ldb;
    int ldsz[4] = {lda, lda, ldb, ldb};

    auto load_chunk = [&](int stage, int k0) {
#pragma unroll
        for (int i = 0; i < 16; i++) {
            const int op = i >> 2;
            const int q = tid + GTH * (i & 3);
            const int r = q >> 2;
            const int c = (q & 3) * 8;
            uint32_t dst = smem_u32 +
                (uint32_t)(((stage * 4 + op) * BUFB + r * SKB + c) * 2);
            const bf16* src = srcs[op] + (size_t)r * ldsz[op] + k0 + c;
            CP_ASYNC16(dst, src);
        }
        CP_COMMIT();
    };

    load_chunk(0, 0);
    CP_WAIT0();
    __syncthreads();

    for (int it = 0; it < kSteps; it++) {
        int s = it & 1;
        const uint32_t stA_h = smem_u32 + (uint32_t)((s * 4 + 0) * BUFB * 2);
        const uint32_t stA_l = smem_u32 + (uint32_t)((s * 4 + 1) * BUFB * 2);
        const uint32_t stB_h = smem_u32 + (uint32_t)((s * 4 + 2) * BUFB * 2);
        const uint32_t stB_l = smem_u32 + (uint32_t)((s * 4 + 3) * BUFB * 2);

#pragma unroll
        for (int kc = 0; kc < 2; kc++) {
            const uint32_t kbase = (uint32_t)(kc * 16);
            uint32_t ah[4][4], al[4][4], bh[8][2], bl[8][2];
#pragma unroll
            for (int mt = 0; mt < 4; mt++) {
                uint32_t ra = (uint32_t)(((wm + mt * 16 + a_row) * SKB + kbase + a_koff) * 2);
                LDSM_X4(ah[mt], stA_h + ra);
                LDSM_X4(al[mt], stA_l + ra);
            }
#pragma unroll
            for (int p = 0; p < 4; p++) {
                uint32_t rb = (uint32_t)(((wn + p * 16 + b_row) * SKB + kbase + b_koff) * 2);
                uint32_t t[4];
                LDSM_X4(t, stB_h + rb);
                bh[2 * p][0] = t[0]; bh[2 * p][1] = t[1];
                bh[2 * p + 1][0] = t[2]; bh[2 * p + 1][1] = t[3];
                LDSM_X4(t, stB_l + rb);
                bl[2 * p][0] = t[0]; bl[2 * p][1] = t[1];
                bl[2 * p + 1][0] = t[2]; bl[2 * p + 1][1] = t[3];
            }
            // prefetch next stage AFTER kc0 frag loads, BEFORE MMAs
            if (kc == 0 && it + 1 < kSteps) load_chunk((it + 1) & 1, (it + 1) * BK);
#pragma unroll
            for (int mt = 0; mt < 4; mt++)
#pragma unroll
                for (int nt = 0; nt < 8; nt++) {
                    MMA_BF16(acc[mt][nt], ah[mt], bh[nt]);
                    MMA_BF16(acc[mt][nt], ah[mt], bl[nt]);
                    MMA_BF16(acc[mt][nt], al[mt], bh[nt]);
                }
        }
        if (it + 1 < kSteps) CP_WAIT0();
        __syncthreads();
    }
}

// ============================================================
// 2-term fp16 GEMM core for PV: A = P (fp16), B = V split (fp16).
// Operands per stage: 0=P, 1=Vh, 2=Vl.
// ============================================================
__device__ __forceinline__ void gemm2_core(
    const f16* __restrict__ Pa, int lda,
    const f16* __restrict__ Bhi, const f16* __restrict__ Blo, int ldb,
    int m0, int n0, int kSteps, float acc[4][8][4]) {
    extern __shared__ bf16 smem[];
    const int tid = threadIdx.x;
    const int wid = tid >> 5;
    const int lane = tid & 31;
    const int wm = (wid & 1) * 64;
    const int wn = (wid >> 1) * 64;

    const uint32_t a_row  = lane & 15;
    const uint32_t a_koff = (uint32_t)((lane >> 4) << 3);
    const uint32_t b_row  = (uint32_t)((lane & 7) + ((lane >> 4) << 3));
    const uint32_t b_koff = (uint32_t)(((lane >> 3) & 1) << 3);

    uint32_t smem_u32 = (uint32_t)__cvta_generic_to_shared(smem);

#pragma unroll
    for (int mt = 0; mt < 4; mt++)
#pragma unroll
        for (int nt = 0; nt < 8; nt++)
#pragma unroll
            for (int c = 0; c < 4; c++) acc[mt][nt][c] = 0.0f;

    const f16* srcs[3];
    srcs[0] = Pa + (size_t)m0 * lda;
    srcs[1] = Bhi + (size_t)n0 * ldb;
    srcs[2] = Blo + (size_t)n0 * ldb;
    int ldsz[3] = {lda, ldb, ldb};

    auto load_chunk = [&](int stage, int k0) {
#pragma unroll
        for (int i = 0; i < 12; i++) {
            const int op = i >> 2;
            const int q = tid + GTH * (i & 3);
            const int r = q >> 2;
            const int c = (q & 3) * 8;
            uint32_t dst = smem_u32 +
                (uint32_t)(((stage * 4 + op) * BUFB + r * SKB + c) * 2);
            const f16* src = srcs[op] + (size_t)r * ldsz[op] + k0 + c;
            CP_ASYNC16(dst, src);
        }
        CP_COMMIT();
    };

    load_chunk(0, 0);
    CP_WAIT0();
    __syncthreads();

    for (int it = 0; it < kSteps; it++) {
        int s = it & 1;
        const uint32_t stA   = smem_u32 + (uint32_t)((s * 4 + 0) * BUFB * 2);
        const uint32_t stB_h = smem_u32 + (uint32_t)((s * 4 + 1) * BUFB * 2);
        const uint32_t stB_l = smem_u32 + (uint32_t)((s * 4 + 2) * BUFB * 2);

#pragma unroll
        for (int kc = 0; kc < 2; kc++) {
            const uint32_t kbase = (uint32_t)(kc * 16);
            uint32_t a[4][4], bh[8][2], bl[8][2];
#pragma unroll
            for (int mt = 0; mt < 4; mt++) {
                uint32_t ra = (uint32_t)(((wm + mt * 16 + a_row) * SKB + kbase + a_koff) * 2);
                LDSM_X4(a[mt], stA + ra);
            }
#pragma unroll
            for (int p = 0; p < 4; p++) {
                uint32_t rb = (uint32_t)(((wn + p * 16 + b_row) * SKB + kbase + b_koff) * 2);
                uint32_t t[4];
                LDSM_X4(t, stB_h + rb);
                bh[2 * p][0] = t[0]; bh[2 * p][1] = t[1];
                bh[2 * p + 1][0] = t[2]; bh[2 * p + 1][1] = t[3];
                LDSM_X4(t, stB_l + rb);
                bl[2 * p][0] = t[0]; bl[2 * p][1] = t[1];
                bl[2 * p + 1][0] = t[2]; bl[2 * p + 1][1] = t[3];
            }
            if (kc == 0 && it + 1 < kSteps) load_chunk((it + 1) & 1, (it + 1) * BK);
#pragma unroll
            for (int mt = 0; mt < 4; mt++)
#pragma unroll
                for (int nt = 0; nt < 8; nt++) {
                    MMA_F16(acc[mt][nt], a[mt], bh[nt]);
                    MMA_F16(acc[mt][nt], a[mt], bl[nt]);
                }
        }
        if (it + 1 < kSteps) CP_WAIT0();
        __syncthreads();
    }
}

// ============================================================
// Combined QKV projection. grid = (DIM/BN, MTOT/BM, 3)
// z=0: Q (rope+split bf16), z=1: K (rope+split bf16),
// z=2: V (smem-staged transposed fp16-split store)
// ============================================================
__global__ __launch_bounds__(GTH, 2)
void qkv_mma_kernel(const bf16* __restrict__ Ahi, const bf16* __restrict__ Alo,
                    const bf16* __restrict__ Whi, const bf16* __restrict__ Wlo,
                    bf16* __restrict__ Qh, bf16* __restrict__ Ql,
                    bf16* __restrict__ Kh, bf16* __restrict__ Kl,
                    f16* __restrict__ Vth, f16* __restrict__ Vtl,
                    const float* __restrict__ Ct, const float* __restrict__ St) {
    const int n0 = blockIdx.x * BN;
    const int m0 = blockIdx.y * BM;
    const int z  = blockIdx.z;
    const size_t nw = (size_t)DIM * DIM;

    float acc[4][8][4];
    gemm3_core(Ahi, Alo, DIM, Whi + z * nw, Wlo + z * nw, DIM, m0, n0, DIM / BK, acc);

    const int tid = threadIdx.x;
    const int wid = tid >> 5;
    const int lane = tid & 31;
    const int grp = lane >> 2;
    const int tig = lane & 3;
    const int wm = (wid & 1) * 64;
    const int wn = (wid >> 1) * 64;

    if (z != 2) {
        bf16* Ohi = (z == 0) ? Qh : Kh;
        bf16* Olo = (z == 0) ? Ql : Kl;
#pragma unroll
        for (int mt = 0; mt < 4; mt++)
#pragma unroll
            for (int nt = 0; nt < 8; nt++)
#pragma unroll
                for (int h = 0; h < 2; h++) {
                    int row = m0 + wm + mt * 16 + grp + 8 * h;
                    int colE = n0 + wn + nt * 8 + tig * 2;
                    float e = acc[mt][nt][2 * h];
                    float o = acc[mt][nt][2 * h + 1];
                    int s = row & (SEQ - 1);
                    int j = colE >> 1;
                    float cth = Ct[(size_t)s * HALF_D + j];
                    float sth = St[(size_t)s * HALF_D + j];
                    float re = e * cth - o * sth;
                    float ro = e * sth + o * cth;
                    bf16 h1, l1, h2, l2;
                    split_bf16(re, h1, l1);
                    split_bf16(ro, h2, l2);
                    size_t p = (size_t)row * DIM + colE;
                    *(bf162*)(Ohi + p) = bf162{h1, h2};
                    *(bf162*)(Olo + p) = bf162{l1, l2};
                }
    } else {
        // V: stage fp32 tile in smem [col][row], coalesced fp16-split stores
        extern __shared__ bf16 smem[];
        float* vbuf = (float*)smem;   // 128 x VSTRIDE floats = 68.1 KB
#pragma unroll
        for (int mt = 0; mt < 4; mt++)
#pragma unroll
            for (int nt = 0; nt < 8; nt++)
#pragma unroll
                for (int h = 0; h < 2; h++) {
                    int rowL = wm + mt * 16 + grp + 8 * h;
                    int colL = wn + nt * 8 + tig * 2;
                    vbuf[colL * VSTRIDE + rowL]       = acc[mt][nt][2 * h];
                    vbuf[(colL + 1) * VSTRIDE + rowL] = acc[mt][nt][2 * h + 1];
                }
        __syncthreads();

        const int bq = m0 >> 12;
        const int sbase = m0 & (SEQ - 1);
        const int col = tid;
        const float* srcc = vbuf + col * VSTRIDE;
        size_t gbase = ((size_t)bq * DIM + n0 + col) * SEQ + sbase;
#pragma unroll
        for (int j0 = 0; j0 < 128; j0 += 8) {
            f16 h8[8], l8[8];
#pragma unroll
            for (int j = 0; j < 8; j++) split_f16(srcc[j0 + j], h8[j], l8[j]);
            *(uint4*)(Vth + gbase + j0) = *(uint4*)h8;
            *(uint4*)(Vtl + gbase + j0) = *(uint4*)l8;
        }
    }
}

// ============================================================
// Scores+exp: E = exp((Q K^T)/32) masked causal, fp16 output.
// grid = (SEQ/BN, SEQ/BM, BATCH)
// ============================================================
__global__ __launch_bounds__(GTH, 2)
void scores_mma_kernel(const bf16* __restrict__ Qhi, const bf16* __restrict__ Qlo,
                       const bf16* __restrict__ Khi, const bf16* __restrict__ Klo,
                       f16* __restrict__ Pf) {
    const int n0 = blockIdx.x * BN;
    const int m0 = blockIdx.y * BM;
    if (n0 > m0) return;
    const int b = blockIdx.z;
    const size_t boff = (size_t)b * SEQ * DIM;

    float acc[4][8][4];
    gemm3_core(Qhi + boff, Qlo + boff, DIM, Khi + boff, Klo + boff, DIM,
               m0, n0, DIM / BK, acc);

    const int tid = threadIdx.x;
    const int wid = tid >> 5;
    const int lane = tid & 31;
    const int grp = lane >> 2;
    const int tig = lane & 3;
    const int wm = (wid & 1) * 64;
    const int wn = (wid >> 1) * 64;
    const float scale = 1.0f / 32.0f;

    f16* Pb = Pf + (size_t)b * SEQ * SEQ;
#pragma unroll
    for (int mt = 0; mt < 4; mt++)
#pragma unroll
        for (int nt = 0; nt < 8; nt++)
#pragma unroll
            for (int h = 0; h < 2; h++) {
                int row = m0 + wm + mt * 16 + grp + 8 * h;
                int col = n0 + wn + nt * 8 + tig * 2;
                float e0 = (col     <= row) ? __expf(acc[mt][nt][2 * h]     * scale) : 0.0f;
                float e1 = (col + 1 <= row) ? __expf(acc[mt][nt][2 * h + 1] * scale) : 0.0f;
                *(f162*)(Pb + (size_t)row * SEQ + col) = __floats2half2_rn(e0, e1);
            }
}

// ============================================================
// Deterministic per-row sum of fp16 exp values. Block per row.
// ============================================================
__global__ __launch_bounds__(NTHREADS)
void rowsum_kernel(const f16* __restrict__ Pf, float* __restrict__ rsum) {
    __shared__ float red[NTHREADS / 32];
    const int rowg = blockIdx.x;
    const int b = rowg >> 12;
    const int i = rowg & (SEQ - 1);
    const f16* p = Pf + ((size_t)b * SEQ + i) * SEQ;
    const int bound = (i & ~127) + 128;
    const int tid = threadIdx.x;
    const int lane = tid & 31;
    const int wrp = tid >> 5;

    float sum = 0.0f;
    for (int j = tid * 2; j < bound; j += NTHREADS * 2) {
        float2 v = __half22float2(*(const f162*)(p + j));
        sum += v.x + v.y;
    }
#pragma unroll
    for (int o = 16; o > 0; o >>= 1) sum += __shfl_xor_sync(~0u, sum, o);
    if (lane == 0) red[wrp] = sum;
    __syncthreads();
    if (tid == 0) {
        float s = 0.0f;
#pragma unroll
        for (int w = 0; w < NTHREADS / 32; w++) s += red[w];
        rsum[rowg] = s;
    }
}

// ============================================================
// PV: O = (E @ V) / rowsum, fp16 2-term MMA, causal-truncated k-loop.
// grid = (DIM/BN, SEQ/BM, BATCH); heavy m-tiles first.
// ============================================================
__global__ __launch_bounds__(GTH, 2)
void pv_mma_kernel(const f16* __restrict__ Pf,
                   const f16* __restrict__ Vth, const f16* __restrict__ Vtl,
                   const float* __restrict__ rsum, float* __restrict__ O) {
    const int n0 = blockIdx.x * BN;
    const int m0 = (int)(gridDim.y - 1 - blockIdx.y) * BM;
    const int b = blockIdx.z;

    float acc[4][8][4];
    gemm2_core(Pf + (size_t)b * SEQ * SEQ, SEQ,
               Vth + (size_t)b * DIM * SEQ, Vtl + (size_t)b * DIM * SEQ, SEQ,
               m0, n0, (m0 + BM) / BK, acc);

    const int tid = threadIdx.x;
    const int wid = tid >> 5;
    const int lane = tid & 31;
    const int grp = lane >> 2;
    const int tig = lane & 3;
    const int wm = (wid & 1) * 64;
    const int wn = (wid >> 1) * 64;

#pragma unroll
    for (int mt = 0; mt < 4; mt++)
#pragma unroll
        for (int nt = 0; nt < 8; nt++)
#pragma unroll
            for (int h = 0; h < 2; h++) {
                int row = m0 + wm + mt * 16 + grp + 8 * h;
                int col = n0 + wn + nt * 8 + tig * 2;
                float inv = 1.0f / rsum[(size_t)b * SEQ + row];
                float2 v;
                v.x = acc[mt][nt][2 * h] * inv;
                v.y = acc[mt][nt][2 * h + 1] * inv;
                *(float2*)(O + ((size_t)b * SEQ + row) * DIM + col) = v;
            }
}

// ============================================================
// Launch
// ============================================================
extern "C" void kernel_launch(void* const* d_in, const int* in_sizes, int n_in,
                              void* d_out, int out_size) {
    const float* x  = (const float*)d_in[0];
    const float* Wq = (const float*)d_in[1];
    const float* Wk = (const float*)d_in[2];
    const float* Wv = (const float*)d_in[3];
    float* out = (float*)d_out;

    bf16 *xh, *xl, *Wh, *Wl, *Qh, *Ql, *Kh, *Kl;
    f16 *Vth, *Vtl, *Pf;
    float *Rs, *Cp, *Sp;
    cudaGetSymbolAddress((void**)&xh, g_xhi);
    cudaGetSymbolAddress((void**)&xl, g_xlo);
    cudaGetSymbolAddress((void**)&Wh, g_Whi);
    cudaGetSymbolAddress((void**)&Wl, g_Wlo);
    cudaGetSymbolAddress((void**)&Qh, g_Qhi);
    cudaGetSymbolAddress((void**)&Ql, g_Qlo);
    cudaGetSymbolAddress((void**)&Kh, g_Khi);
    cudaGetSymbolAddress((void**)&Kl, g_Klo);
    cudaGetSymbolAddress((void**)&Vth, g_Vth);
    cudaGetSymbolAddress((void**)&Vtl, g_Vtl);
    cudaGetSymbolAddress((void**)&Pf, g_Pf);
    cudaGetSymbolAddress((void**)&Rs, g_rsum);
    cudaGetSymbolAddress((void**)&Cp, g_cos);
    cudaGetSymbolAddress((void**)&Sp, g_sin);

    cudaFuncSetAttribute(qkv_mma_kernel,    cudaFuncAttributeMaxDynamicSharedMemorySize, SMEM_BYTES);
    cudaFuncSetAttribute(scores_mma_kernel, cudaFuncAttributeMaxDynamicSharedMemorySize, SMEM_BYTES);
    cudaFuncSetAttribute(pv_mma_kernel,     cudaFuncAttributeMaxDynamicSharedMemorySize, SMEM_BYTES);

    // 1) trig tables
    {
        int total = SEQ * HALF_D;
        trig_table_kernel<<<(total + 255) / 256, 256>>>(Cp, Sp);
    }
    // 2) split x
    {
        int nx = MTOT * DIM;
        split_kernel<<<(nx + 255) / 256, 256>>>(x, xh, xl, nx);
    }
    // 3) split all weights (one launch)
    {
        int n3 = 3 * DIM * DIM;
        split_w3_kernel<<<(n3 + 255) / 256, 256>>>(Wq, Wk, Wv, Wh, Wl);
    }

    // 4) QKV projections (single launch, grid.z selects Q/K/V)
    {
        dim3 grid(DIM / BN, MTOT / BM, 3);   // (8, 128, 3)
        qkv_mma_kernel<<<grid, GTH, SMEM_BYTES>>>(xh, xl, Wh, Wl,
                                                  Qh, Ql, Kh, Kl, Vth, Vtl,
                                                  Cp, Sp);
    }
    // 5) scores + exp + causal mask (fp16 output, no softmax pass)
    {
        dim3 grid(SEQ / BN, SEQ / BM, BATCH);
        scores_mma_kernel<<<grid, GTH, SMEM_BYTES>>>(Qh, Ql, Kh, Kl, Pf);
    }
    // 6) deterministic row sums
    rowsum_kernel<<<BATCH * SEQ, NTHREADS>>>(Pf, Rs);

    // 7) O = (E @ V) / rowsum
    {
        dim3 grid(DIM / BN, SEQ / BM, BATCH);
        pv_mma_kernel<<<grid, GTH, SMEM_BYTES>>>(Pf, Vth, Vtl, Rs, out);
    }
}

// round 15
// speedup vs baseline: 1.3431x; 1.2016x over previous
#include <cuda_runtime.h>
#include <cuda_fp16.h>
#include <math.h>
#include <stdint.h>

typedef __half f16;
typedef __half2 f162;

// Problem constants
#define BATCH 4
#define SEQ   4096
#define DIM   1024
#define MTOT  (BATCH * SEQ)     // 16384
#define HALF_D (DIM / 2)        // 512

// GEMM tiling: 128x128 CTA tile, 4 warps of 64x64
#define BM 128
#define BN 128
#define BK 32
#define GTH 128                         // gemm block threads (4 warps)
#define NTHREADS 256                    // helper-kernel block size
#define SKB 40                          // padded smem row stride (f16) = 80 B
#define BUFB (BM * SKB)                 // 5120 f16 per operand buffer
#define VSTRIDE 133                     // fp32 stage buffer column stride
#define SMEM_BYTES (128 * VSTRIDE * 4)  // 68096 B >= 2*3*BUFB*2 = 61440
// pipeline needs 2 stages x 3 operands x 10240 B = 61440 <= SMEM_BYTES

// -------- device scratch (no cudaMalloc allowed) --------
__device__ f16  g_xh[(size_t)MTOT * DIM];
__device__ f16  g_xl[(size_t)MTOT * DIM];
__device__ f16  g_Wf[(size_t)3 * DIM * DIM];   // Wq,Wk,Wv single f16
__device__ f16  g_Qh[(size_t)MTOT * DIM];
__device__ f16  g_Ql[(size_t)MTOT * DIM];
__device__ f16  g_Kf[(size_t)MTOT * DIM];      // K single f16
__device__ f16  g_Vth[(size_t)MTOT * DIM];     // fp16 split V^T [b][dim][seq]
__device__ f16  g_Vtl[(size_t)MTOT * DIM];
__device__ f16  g_Pf[(size_t)BATCH * SEQ * SEQ];   // unnormalized exp(scores)
__device__ float g_rsum[(size_t)MTOT];
__device__ float g_cos[(size_t)SEQ * HALF_D];
__device__ float g_sin[(size_t)SEQ * HALF_D];

// ============================================================
// helpers
// ============================================================
__device__ __forceinline__ void split_f16(float x, f16& hi, f16& lo) {
    hi = __float2half_rn(x);
    lo = __float2half_rn(x - __half2float(hi));
}

#define MMA_F16(D, A, B)                                                    \
    asm volatile(                                                           \
        "mma.sync.aligned.m16n8k16.row.col.f32.f16.f16.f32 "                \
        "{%0,%1,%2,%3}, {%4,%5,%6,%7}, {%8,%9}, {%0,%1,%2,%3};"             \
        : "+f"((D)[0]), "+f"((D)[1]), "+f"((D)[2]), "+f"((D)[3])            \
        : "r"((A)[0]), "r"((A)[1]), "r"((A)[2]), "r"((A)[3]),               \
          "r"((B)[0]), "r"((B)[1]))

#define LDSM_X4(R, addr)                                                    \
    asm volatile(                                                           \
        "ldmatrix.sync.aligned.m8n8.x4.shared.b16 {%0,%1,%2,%3}, [%4];"     \
        : "=r"((R)[0]), "=r"((R)[1]), "=r"((R)[2]), "=r"((R)[3])            \
        : "r"(addr))

#define CP_ASYNC16(dst, src)                                                \
    asm volatile("cp.async.cg.shared.global [%0], [%1], 16;"                \
                 :: "r"(dst), "l"(src))
#define CP_COMMIT() asm volatile("cp.async.commit_group;")
#define CP_WAIT0()  asm volatile("cp.async.wait_group 0;")

// ============================================================
// RoPE cos/sin table (double precision generation)
// ============================================================
__global__ void trig_table_kernel(float* ct, float* st) {
    int idx = blockIdx.x * blockDim.x + threadIdx.x;
    if (idx >= SEQ * HALF_D) return;
    int s = idx / HALF_D;
    int j = idx % HALF_D;
    double inv = exp(-((double)(2 * j) / (double)DIM) * 9.210340371976184);
    double ang = (double)s * inv;
    double sv, cv;
    sincos(ang, &sv, &cv);
    ct[idx] = (float)cv;
    st[idx] = (float)sv;
}

// ============================================================
// Split fp32 x into f16 hi/lo (exact 2-term representation)
// ============================================================
__global__ void split_x_kernel(const float* __restrict__ src,
                               f16* __restrict__ hi, f16* __restrict__ lo,
                               int n) {
    int i = blockIdx.x * blockDim.x + threadIdx.x;
    if (i >= n) return;
    f16 h, l;
    split_f16(src[i], h, l);
    hi[i] = h;
    lo[i] = l;
}

// Convert three weight matrices to single f16 in one launch
__global__ void conv_w3_kernel(const float* __restrict__ Wq,
                               const float* __restrict__ Wk,
                               const float* __restrict__ Wv,
                               f16* __restrict__ Wf) {
    const int nw = DIM * DIM;
    int i = blockIdx.x * blockDim.x + threadIdx.x;
    if (i >= 3 * nw) return;
    const float* src = (i < nw) ? Wq : (i < 2 * nw) ? Wk : Wv;
    float v = src[i >= 2 * nw ? i - 2 * nw : (i >= nw ? i - nw : i)];
    Wf[i] = __float2half_rn(v);
}

// ============================================================
// Unified 2-term fp16 GEMM core.
// MODE 0 (A split):  acc += T0·T2 + T1·T2   (T0,T1 rows = m; T2 rows = n)
// MODE 1 (B split):  acc += T0·T1 + T0·T2   (T0 rows = m; T1,T2 rows = n)
// Callers pass pointers already offset to their m0/n0 rows.
// ============================================================
template <int MODE>
__device__ __forceinline__ void gemm2s_core(
    const f16* __restrict__ S0, int ld0,
    const f16* __restrict__ S1, int ld1,
    const f16* __restrict__ S2, int ld2,
    int kSteps, float acc[4][8][4]) {
    extern __shared__ f16 smem[];
    const int tid = threadIdx.x;
    const int wid = tid >> 5;
    const int lane = tid & 31;
    const int wm = (wid & 1) * 64;
    const int wn = (wid >> 1) * 64;

    const uint32_t a_row  = lane & 15;
    const uint32_t a_koff = (uint32_t)((lane >> 4) << 3);
    const uint32_t b_row  = (uint32_t)((lane & 7) + ((lane >> 4) << 3));
    const uint32_t b_koff = (uint32_t)(((lane >> 3) & 1) << 3);

    uint32_t smem_u32 = (uint32_t)__cvta_generic_to_shared(smem);

#pragma unroll
    for (int mt = 0; mt < 4; mt++)
#pragma unroll
        for (int nt = 0; nt < 8; nt++)
#pragma unroll
            for (int c = 0; c < 4; c++) acc[mt][nt][c] = 0.0f;

    const f16* srcs[3] = {S0, S1, S2};
    const int ldsz[3] = {ld0, ld1, ld2};

    auto load_chunk = [&](int stage, int k0) {
#pragma unroll
        for (int i = 0; i < 12; i++) {
            const int op = i >> 2;
            const int q = tid + GTH * (i & 3);       // 0..511 per operand
            const int r = q >> 2;                    // row 0..127
            const int c = (q & 3) * 8;               // col 0,8,16,24
            uint32_t dst = smem_u32 +
                (uint32_t)(((stage * 3 + op) * BUFB + r * SKB + c) * 2);
            const f16* src = srcs[op] + (size_t)r * ldsz[op] + k0 + c;
            CP_ASYNC16(dst, src);
        }
        CP_COMMIT();
    };

    load_chunk(0, 0);
    CP_WAIT0();
    __syncthreads();

    for (int it = 0; it < kSteps; it++) {
        int s = it & 1;
        if (it + 1 < kSteps) load_chunk((it + 1) & 1, (it + 1) * BK);

        const uint32_t st0 = smem_u32 + (uint32_t)((s * 3 + 0) * BUFB * 2);
        const uint32_t st1 = smem_u32 + (uint32_t)((s * 3 + 1) * BUFB * 2);
        const uint32_t st2 = smem_u32 + (uint32_t)((s * 3 + 2) * BUFB * 2);

#pragma unroll
        for (int kc = 0; kc < 2; kc++) {
            const uint32_t kbase = (uint32_t)(kc * 16);
            if (MODE == 0) {
                uint32_t a0[4][4], a1[4][4], b[8][2];
#pragma unroll
                for (int mt = 0; mt < 4; mt++) {
                    uint32_t ra = (uint32_t)(((wm + mt * 16 + a_row) * SKB + kbase + a_koff) * 2);
                    LDSM_X4(a0[mt], st0 + ra);
                    LDSM_X4(a1[mt], st1 + ra);
                }
#pragma unroll
                for (int p = 0; p < 4; p++) {
                    uint32_t rb = (uint32_t)(((wn + p * 16 + b_row) * SKB + kbase + b_koff) * 2);
                    uint32_t t[4];
                    LDSM_X4(t, st2 + rb);
                    b[2 * p][0] = t[0]; b[2 * p][1] = t[1];
                    b[2 * p + 1][0] = t[2]; b[2 * p + 1][1] = t[3];
                }
#pragma unroll
                for (int mt = 0; mt < 4; mt++)
#pragma unroll
                    for (int nt = 0; nt < 8; nt++) {
                        MMA_F16(acc[mt][nt], a0[mt], b[nt]);
                        MMA_F16(acc[mt][nt], a1[mt], b[nt]);
                    }
            } else {
                uint32_t a[4][4], b0[8][2], b1[8][2];
#pragma unroll
                for (int mt = 0; mt < 4; mt++) {
                    uint32_t ra = (uint32_t)(((wm + mt * 16 + a_row) * SKB + kbase + a_koff) * 2);
                    LDSM_X4(a[mt], st0 + ra);
                }
#pragma unroll
                for (int p = 0; p < 4; p++) {
                    uint32_t rb = (uint32_t)(((wn + p * 16 + b_row) * SKB + kbase + b_koff) * 2);
                    uint32_t t[4];
                    LDSM_X4(t, st1 + rb);
                    b0[2 * p][0] = t[0]; b0[2 * p][1] = t[1];
                    b0[2 * p + 1][0] = t[2]; b0[2 * p + 1][1] = t[3];
                    LDSM_X4(t, st2 + rb);
                    b1[2 * p][0] = t[0]; b1[2 * p][1] = t[1];
                    b1[2 * p + 1][0] = t[2]; b1[2 * p + 1][1] = t[3];
                }
#pragma unroll
                for (int mt = 0; mt < 4; mt++)
#pragma unroll
                    for (int nt = 0; nt < 8; nt++) {
                        MMA_F16(acc[mt][nt], a[mt], b0[nt]);
                        MMA_F16(acc[mt][nt], a[mt], b1[nt]);
                    }
            }
        }
        if (it + 1 < kSteps) CP_WAIT0();
        __syncthreads();
    }
}

// ============================================================
// Combined QKV projection. grid = (DIM/BN, MTOT/BM, 3)
// z=0: Q -> rope + split-2 f16;  z=1: K -> rope + single f16;
// z=2: V -> smem-staged transposed split-2 f16
// ============================================================
__global__ __launch_bounds__(GTH, 2)
void qkv_mma_kernel(const f16* __restrict__ xh, const f16* __restrict__ xl,
                    const f16* __restrict__ Wf,
                    f16* __restrict__ Qh, f16* __restrict__ Ql,
                    f16* __restrict__ Kf,
                    f16* __restrict__ Vth, f16* __restrict__ Vtl,
                    const float* __restrict__ Ct, const float* __restrict__ St) {
    const int n0 = blockIdx.x * BN;
    const int m0 = blockIdx.y * BM;
    const int z  = blockIdx.z;
    const size_t nw = (size_t)DIM * DIM;

    float acc[4][8][4];
    gemm2s_core<0>(xh + (size_t)m0 * DIM, DIM,
                   xl + (size_t)m0 * DIM, DIM,
                   Wf + z * nw + (size_t)n0 * DIM, DIM,
                   DIM / BK, acc);

    const int tid = threadIdx.x;
    const int wid = tid >> 5;
    const int lane = tid & 31;
    const int grp = lane >> 2;
    const int tig = lane & 3;
    const int wm = (wid & 1) * 64;
    const int wn = (wid >> 1) * 64;

    if (z != 2) {
#pragma unroll
        for (int mt = 0; mt < 4; mt++)
#pragma unroll
            for (int nt = 0; nt < 8; nt++)
#pragma unroll
                for (int h = 0; h < 2; h++) {
                    int row = m0 + wm + mt * 16 + grp + 8 * h;
                    int colE = n0 + wn + nt * 8 + tig * 2;
                    float e = acc[mt][nt][2 * h];
                    float o = acc[mt][nt][2 * h + 1];
                    int s = row & (SEQ - 1);
                    int j = colE >> 1;
                    float cth = Ct[(size_t)s * HALF_D + j];
                    float sth = St[(size_t)s * HALF_D + j];
                    float re = e * cth - o * sth;
                    float ro = e * sth + o * cth;
                    size_t p = (size_t)row * DIM + colE;
                    if (z == 0) {
                        f16 h1, l1, h2, l2;
                        split_f16(re, h1, l1);
                        split_f16(ro, h2, l2);
                        *(f162*)(Qh + p) = f162{h1, h2};
                        *(f162*)(Ql + p) = f162{l1, l2};
                    } else {
                        *(f162*)(Kf + p) = __floats2half2_rn(re, ro);
                    }
                }
    } else {
        // V: stage fp32 tile in smem [col][row], coalesced f16-split stores
        extern __shared__ f16 smem[];
        float* vbuf = (float*)smem;   // 128 x VSTRIDE floats = 68096 B
#pragma unroll
        for (int mt = 0; mt < 4; mt++)
#pragma unroll
            for (int nt = 0; nt < 8; nt++)
#pragma unroll
                for (int h = 0; h < 2; h++) {
                    int rowL = wm + mt * 16 + grp + 8 * h;
                    int colL = wn + nt * 8 + tig * 2;
                    vbuf[colL * VSTRIDE + rowL]       = acc[mt][nt][2 * h];
                    vbuf[(colL + 1) * VSTRIDE + rowL] = acc[mt][nt][2 * h + 1];
                }
        __syncthreads();

        const int bq = m0 >> 12;
        const int sbase = m0 & (SEQ - 1);
        const int col = tid;
        const float* srcc = vbuf + col * VSTRIDE;
        size_t gbase = ((size_t)bq * DIM + n0 + col) * SEQ + sbase;
#pragma unroll
        for (int j0 = 0; j0 < 128; j0 += 8) {
            f16 h8[8], l8[8];
#pragma unroll
            for (int j = 0; j < 8; j++) split_f16(srcc[j0 + j], h8[j], l8[j]);
            *(uint4*)(Vth + gbase + j0) = *(uint4*)h8;
            *(uint4*)(Vtl + gbase + j0) = *(uint4*)l8;
        }
    }
}

// ============================================================
// Scores+exp: E = exp((Q K^T)/32) masked causal, fp16 output.
// A = Q split-2 (exact), B = K single. grid = (SEQ/BN, SEQ/BM, BATCH)
// ============================================================
__global__ __launch_bounds__(GTH, 2)
void scores_mma_kernel(const f16* __restrict__ Qh, const f16* __restrict__ Ql,
                       const f16* __restrict__ Kf, f16* __restrict__ Pf) {
    const int n0 = blockIdx.x * BN;
    const int m0 = blockIdx.y * BM;
    if (n0 > m0) return;
    const int b = blockIdx.z;
    const size_t boff = (size_t)b * SEQ * DIM;

    float acc[4][8][4];
    gemm2s_core<0>(Qh + boff + (size_t)m0 * DIM, DIM,
                   Ql + boff + (size_t)m0 * DIM, DIM,
                   Kf + boff + (size_t)n0 * DIM, DIM,
                   DIM / BK, acc);

    const int tid = threadIdx.x;
    const int wid = tid >> 5;
    const int lane = tid & 31;
    const int grp = lane >> 2;
    const int tig = lane & 3;
    const int wm = (wid & 1) * 64;
    const int wn = (wid >> 1) * 64;
    const float scale = 1.0f / 32.0f;

    f16* Pb = Pf + (size_t)b * SEQ * SEQ;
#pragma unroll
    for (int mt = 0; mt < 4; mt++)
#pragma unroll
        for (int nt = 0; nt < 8; nt++)
#pragma unroll
            for (int h = 0; h < 2; h++) {
                int row = m0 + wm + mt * 16 + grp + 8 * h;
                int col = n0 + wn + nt * 8 + tig * 2;
                float e0 = (col     <= row) ? __expf(acc[mt][nt][2 * h]     * scale) : 0.0f;
                float e1 = (col + 1 <= row) ? __expf(acc[mt][nt][2 * h + 1] * scale) : 0.0f;
                *(f162*)(Pb + (size_t)row * SEQ + col) = __floats2half2_rn(e0, e1);
            }
}

// ============================================================
// Deterministic per-row sum of fp16 exp values. Block per row.
// ============================================================
__global__ __launch_bounds__(NTHREADS)
void rowsum_kernel(const f16* __restrict__ Pf, float* __restrict__ rsum) {
    __shared__ float red[NTHREADS / 32];
    const int rowg = blockIdx.x;
    const int b = rowg >> 12;
    const int i = rowg & (SEQ - 1);
    const f16* p = Pf + ((size_t)b * SEQ + i) * SEQ;
    const int bound = (i & ~127) + 128;
    const int tid = threadIdx.x;
    const int lane = tid & 31;
    const int wrp = tid >> 5;

    float sum = 0.0f;
    for (int j = tid * 2; j < bound; j += NTHREADS * 2) {
        float2 v = __half22float2(*(const f162*)(p + j));
        sum += v.x + v.y;
    }
#pragma unroll
    for (int o = 16; o > 0; o >>= 1) sum += __shfl_xor_sync(~0u, sum, o);
    if (lane == 0) red[wrp] = sum;
    __syncthreads();
    if (tid == 0) {
        float s = 0.0f;
#pragma unroll
        for (int w = 0; w < NTHREADS / 32; w++) s += red[w];
        rsum[rowg] = s;
    }
}

// ============================================================
// PV: O = (E @ V) / rowsum, A = P single, B = V split-2.
// grid = (DIM/BN, SEQ/BM, BATCH); heavy m-tiles first.
// ============================================================
__global__ __launch_bounds__(GTH, 2)
void pv_mma_kernel(const f16* __restrict__ Pf,
                   const f16* __restrict__ Vth, const f16* __restrict__ Vtl,
                   const float* __restrict__ rsum, float* __restrict__ O) {
    const int n0 = blockIdx.x * BN;
    const int m0 = (int)(gridDim.y - 1 - blockIdx.y) * BM;
    const int b = blockIdx.z;

    float acc[4][8][4];
    gemm2s_core<1>(Pf + (size_t)b * SEQ * SEQ + (size_t)m0 * SEQ, SEQ,
                   Vth + (size_t)b * DIM * SEQ + (size_t)n0 * SEQ, SEQ,
                   Vtl + (size_t)b * DIM * SEQ + (size_t)n0 * SEQ, SEQ,
                   (m0 + BM) / BK, acc);

    const int tid = threadIdx.x;
    const int wid = tid >> 5;
    const int lane = tid & 31;
    const int grp = lane >> 2;
    const int tig = lane & 3;
    const int wm = (wid & 1) * 64;
    const int wn = (wid >> 1) * 64;

#pragma unroll
    for (int mt = 0; mt < 4; mt++)
#pragma unroll
        for (int nt = 0; nt < 8; nt++)
#pragma unroll
            for (int h = 0; h < 2; h++) {
                int row = m0 + wm + mt * 16 + grp + 8 * h;
                int col = n0 + wn + nt * 8 + tig * 2;
                float inv = 1.0f / rsum[(size_t)b * SEQ + row];
                float2 v;
                v.x = acc[mt][nt][2 * h] * inv;
                v.y = acc[mt][nt][2 * h + 1] * inv;
                *(float2*)(O + ((size_t)b * SEQ + row) * DIM + col) = v;
            }
}

// ============================================================
// Launch
// ============================================================
extern "C" void kernel_launch(void* const* d_in, const int* in_sizes, int n_in,
                              void* d_out, int out_size) {
    const float* x  = (const float*)d_in[0];
    const float* Wq = (const float*)d_in[1];
    const float* Wk = (const float*)d_in[2];
    const float* Wv = (const float*)d_in[3];
    float* out = (float*)d_out;

    f16 *xh, *xl, *Wf, *Qh, *Ql, *Kf, *Vth, *Vtl, *Pf;
    float *Rs, *Cp, *Sp;
    cudaGetSymbolAddress((void**)&xh, g_xh);
    cudaGetSymbolAddress((void**)&xl, g_xl);
    cudaGetSymbolAddress((void**)&Wf, g_Wf);
    cudaGetSymbolAddress((void**)&Qh, g_Qh);
    cudaGetSymbolAddress((void**)&Ql, g_Ql);
    cudaGetSymbolAddress((void**)&Kf, g_Kf);
    cudaGetSymbolAddress((void**)&Vth, g_Vth);
    cudaGetSymbolAddress((void**)&Vtl, g_Vtl);
    cudaGetSymbolAddress((void**)&Pf, g_Pf);
    cudaGetSymbolAddress((void**)&Rs, g_rsum);
    cudaGetSymbolAddress((void**)&Cp, g_cos);
    cudaGetSymbolAddress((void**)&Sp, g_sin);

    cudaFuncSetAttribute(qkv_mma_kernel,    cudaFuncAttributeMaxDynamicSharedMemorySize, SMEM_BYTES);
    cudaFuncSetAttribute(scores_mma_kernel, cudaFuncAttributeMaxDynamicSharedMemorySize, SMEM_BYTES);
    cudaFuncSetAttribute(pv_mma_kernel,     cudaFuncAttributeMaxDynamicSharedMemorySize, SMEM_BYTES);

    // 1) trig tables
    {
        int total = SEQ * HALF_D;
        trig_table_kernel<<<(total + 255) / 256, 256>>>(Cp, Sp);
    }
    // 2) split x into f16 hi/lo
    {
        int nx = MTOT * DIM;
        split_x_kernel<<<(nx + 255) / 256, 256>>>(x, xh, xl, nx);
    }
    // 3) convert all weights to f16 (one launch)
    {
        int n3 = 3 * DIM * DIM;
        conv_w3_kernel<<<(n3 + 255) / 256, 256>>>(Wq, Wk, Wv, Wf);
    }

    // 4) QKV projections (single launch, grid.z selects Q/K/V)
    {
        dim3 grid(DIM / BN, MTOT / BM, 3);   // (8, 128, 3)
        qkv_mma_kernel<<<grid, GTH, SMEM_BYTES>>>(xh, xl, Wf,
                                                  Qh, Ql, Kf, Vth, Vtl,
                                                  Cp, Sp);
    }
    // 5) scores + exp + causal mask (fp16 output)
    {
        dim3 grid(SEQ / BN, SEQ / BM, BATCH);
        scores_mma_kernel<<<grid, GTH, SMEM_BYTES>>>(Qh, Ql, Kf, Pf);
    }
    // 6) deterministic row sums
    rowsum_kernel<<<BATCH * SEQ, NTHREADS>>>(Pf, Rs);

    // 7) O = (E @ V) / rowsum
    {
        dim3 grid(DIM / BN, SEQ / BM, BATCH);
        pv_mma_kernel<<<grid, GTH, SMEM_BYTES>>>(Pf, Vth, Vtl, Rs, out);
    }
}

// round 16
// speedup vs baseline: 1.4338x; 1.0675x over previous
#include <cuda_runtime.h>
#include <cuda_fp16.h>
#include <math.h>
#include <stdint.h>

typedef __half f16;
typedef __half2 f162;

// Problem constants
#define BATCH 4
#define SEQ   4096
#define DIM   1024
#define MTOT  (BATCH * SEQ)     // 16384
#define HALF_D (DIM / 2)        // 512

// GEMM tiling: 128x128 CTA tile, 4 warps of 64x64, BK=64
#define BM 128
#define BN 128
#define BK 64
#define GTH 128                         // gemm block threads (4 warps)
#define NTHREADS 256                    // helper-kernel block size
#define SKB 72                          // padded smem row stride (f16) = 144 B (36 words == 4 mod 8)
#define BUFB (BM * SKB)                 // 9216 f16 per operand buffer
#define VSTRIDE 133                     // fp32 stage buffer column stride
#define SMEM_BYTES (2 * 3 * BUFB * 2)   // 2 stages x 3 operands = 110592 B
// V staging buffer (128*VSTRIDE*4 = 68096 B) reuses the pipeline smem.

// -------- device scratch (no cudaMalloc allowed) --------
__device__ f16  g_xh[(size_t)MTOT * DIM];
__device__ f16  g_xl[(size_t)MTOT * DIM];
__device__ f16  g_Wf[(size_t)3 * DIM * DIM];   // Wq,Wk,Wv single f16
__device__ f16  g_Qh[(size_t)MTOT * DIM];
__device__ f16  g_Ql[(size_t)MTOT * DIM];
__device__ f16  g_Kf[(size_t)MTOT * DIM];      // K single f16
__device__ f16  g_Vth[(size_t)MTOT * DIM];     // fp16 split V^T [b][dim][seq]
__device__ f16  g_Vtl[(size_t)MTOT * DIM];
__device__ f16  g_Pf[(size_t)BATCH * SEQ * SEQ];   // unnormalized exp(scores)
__device__ float g_rsum[(size_t)MTOT];
__device__ float g_cos[(size_t)SEQ * HALF_D];
__device__ float g_sin[(size_t)SEQ * HALF_D];

// ============================================================
// helpers
// ============================================================
__device__ __forceinline__ void split_f16(float x, f16& hi, f16& lo) {
    hi = __float2half_rn(x);
    lo = __float2half_rn(x - __half2float(hi));
}

#define MMA_F16(D, A, B)                                                    \
    asm volatile(                                                           \
        "mma.sync.aligned.m16n8k16.row.col.f32.f16.f16.f32 "                \
        "{%0,%1,%2,%3}, {%4,%5,%6,%7}, {%8,%9}, {%0,%1,%2,%3};"             \
        : "+f"((D)[0]), "+f"((D)[1]), "+f"((D)[2]), "+f"((D)[3])            \
        : "r"((A)[0]), "r"((A)[1]), "r"((A)[2]), "r"((A)[3]),               \
          "r"((B)[0]), "r"((B)[1]))

#define LDSM_X4(R, addr)                                                    \
    asm volatile(                                                           \
        "ldmatrix.sync.aligned.m8n8.x4.shared.b16 {%0,%1,%2,%3}, [%4];"     \
        : "=r"((R)[0]), "=r"((R)[1]), "=r"((R)[2]), "=r"((R)[3])            \
        : "r"(addr))

#define CP_ASYNC16(dst, src)                                                \
    asm volatile("cp.async.cg.shared.global [%0], [%1], 16;"                \
                 :: "r"(dst), "l"(src))
#define CP_COMMIT() asm volatile("cp.async.commit_group;")
#define CP_WAIT0()  asm volatile("cp.async.wait_group 0;")

// ============================================================
// RoPE cos/sin table (double precision generation)
// ============================================================
__global__ void trig_table_kernel(float* ct, float* st) {
    int idx = blockIdx.x * blockDim.x + threadIdx.x;
    if (idx >= SEQ * HALF_D) return;
    int s = idx / HALF_D;
    int j = idx % HALF_D;
    double inv = exp(-((double)(2 * j) / (double)DIM) * 9.210340371976184);
    double ang = (double)s * inv;
    double sv, cv;
    sincos(ang, &sv, &cv);
    ct[idx] = (float)cv;
    st[idx] = (float)sv;
}

// ============================================================
// Split fp32 x into f16 hi/lo (exact 2-term representation)
// ============================================================
__global__ void split_x_kernel(const float* __restrict__ src,
                               f16* __restrict__ hi, f16* __restrict__ lo,
                               int n) {
    int i = blockIdx.x * blockDim.x + threadIdx.x;
    if (i >= n) return;
    f16 h, l;
    split_f16(src[i], h, l);
    hi[i] = h;
    lo[i] = l;
}

// Convert three weight matrices to single f16 in one launch
__global__ void conv_w3_kernel(const float* __restrict__ Wq,
                               const float* __restrict__ Wk,
                               const float* __restrict__ Wv,
                               f16* __restrict__ Wf) {
    const int nw = DIM * DIM;
    int i = blockIdx.x * blockDim.x + threadIdx.x;
    if (i >= 3 * nw) return;
    const float* src = (i < nw) ? Wq : (i < 2 * nw) ? Wk : Wv;
    float v = src[i >= 2 * nw ? i - 2 * nw : (i >= nw ? i - nw : i)];
    Wf[i] = __float2half_rn(v);
}

// ============================================================
// Unified 2-term fp16 GEMM core, BK=64.
// MODE 0 (A split):  acc += T0·T2 + T1·T2   (T0,T1 rows = m; T2 rows = n)
// MODE 1 (B split):  acc += T0·T1 + T0·T2   (T0 rows = m; T1,T2 rows = n)
// Callers pass pointers already offset to their m0/n0 rows.
// ============================================================
template <int MODE>
__device__ __forceinline__ void gemm2s_core(
    const f16* __restrict__ S0, int ld0,
    const f16* __restrict__ S1, int ld1,
    const f16* __restrict__ S2, int ld2,
    int kSteps, float acc[4][8][4]) {
    extern __shared__ f16 smem[];
    const int tid = threadIdx.x;
    const int wid = tid >> 5;
    const int lane = tid & 31;
    const int wm = (wid & 1) * 64;
    const int wn = (wid >> 1) * 64;

    const uint32_t a_row  = lane & 15;
    const uint32_t a_koff = (uint32_t)((lane >> 4) << 3);
    const uint32_t b_row  = (uint32_t)((lane & 7) + ((lane >> 4) << 3));
    const uint32_t b_koff = (uint32_t)(((lane >> 3) & 1) << 3);

    uint32_t smem_u32 = (uint32_t)__cvta_generic_to_shared(smem);

#pragma unroll
    for (int mt = 0; mt < 4; mt++)
#pragma unroll
        for (int nt = 0; nt < 8; nt++)
#pragma unroll
            for (int c = 0; c < 4; c++) acc[mt][nt][c] = 0.0f;

    const f16* srcs[3] = {S0, S1, S2};
    const int ldsz[3] = {ld0, ld1, ld2};

    auto load_chunk = [&](int stage, int k0) {
        // per operand: 128 rows x 64 f16 = 1024 x 16B chunks; 8 per thread
#pragma unroll
        for (int i = 0; i < 24; i++) {
            const int op = i >> 3;
            const int q = tid + GTH * (i & 7);       // 0..1023 per operand
            const int r = q >> 3;                    // row 0..127
            const int c = (q & 7) * 8;               // col 0,8,...,56
            uint32_t dst = smem_u32 +
                (uint32_t)(((stage * 3 + op) * BUFB + r * SKB + c) * 2);
            const f16* src = srcs[op] + (size_t)r * ldsz[op] + k0 + c;
            CP_ASYNC16(dst, src);
        }
        CP_COMMIT();
    };

    load_chunk(0, 0);
    CP_WAIT0();
    __syncthreads();

    for (int it = 0; it < kSteps; it++) {
        int s = it & 1;
        if (it + 1 < kSteps) load_chunk((it + 1) & 1, (it + 1) * BK);

        const uint32_t st0 = smem_u32 + (uint32_t)((s * 3 + 0) * BUFB * 2);
        const uint32_t st1 = smem_u32 + (uint32_t)((s * 3 + 1) * BUFB * 2);
        const uint32_t st2 = smem_u32 + (uint32_t)((s * 3 + 2) * BUFB * 2);

#pragma unroll
        for (int kc = 0; kc < 4; kc++) {          // four k16 chunks per BK=64
            const uint32_t kbase = (uint32_t)(kc * 16);
            if (MODE == 0) {
                uint32_t a0[4][4], a1[4][4], b[8][2];
#pragma unroll
                for (int mt = 0; mt < 4; mt++) {
                    uint32_t ra = (uint32_t)(((wm + mt * 16 + a_row) * SKB + kbase + a_koff) * 2);
                    LDSM_X4(a0[mt], st0 + ra);
                    LDSM_X4(a1[mt], st1 + ra);
                }
#pragma unroll
                for (int p = 0; p < 4; p++) {
                    uint32_t rb = (uint32_t)(((wn + p * 16 + b_row) * SKB + kbase + b_koff) * 2);
                    uint32_t t[4];
                    LDSM_X4(t, st2 + rb);
                    b[2 * p][0] = t[0]; b[2 * p][1] = t[1];
                    b[2 * p + 1][0] = t[2]; b[2 * p + 1][1] = t[3];
                }
#pragma unroll
                for (int mt = 0; mt < 4; mt++)
#pragma unroll
                    for (int nt = 0; nt < 8; nt++) {
                        MMA_F16(acc[mt][nt], a0[mt], b[nt]);
                        MMA_F16(acc[mt][nt], a1[mt], b[nt]);
                    }
            } else {
                uint32_t a[4][4], b0[8][2], b1[8][2];
#pragma unroll
                for (int mt = 0; mt < 4; mt++) {
                    uint32_t ra = (uint32_t)(((wm + mt * 16 + a_row) * SKB + kbase + a_koff) * 2);
                    LDSM_X4(a[mt], st0 + ra);
                }
#pragma unroll
                for (int p = 0; p < 4; p++) {
                    uint32_t rb = (uint32_t)(((wn + p * 16 + b_row) * SKB + kbase + b_koff) * 2);
                    uint32_t t[4];
                    LDSM_X4(t, st1 + rb);
                    b0[2 * p][0] = t[0]; b0[2 * p][1] = t[1];
                    b0[2 * p + 1][0] = t[2]; b0[2 * p + 1][1] = t[3];
                    LDSM_X4(t, st2 + rb);
                    b1[2 * p][0] = t[0]; b1[2 * p][1] = t[1];
                    b1[2 * p + 1][0] = t[2]; b1[2 * p + 1][1] = t[3];
                }
#pragma unroll
                for (int mt = 0; mt < 4; mt++)
#pragma unroll
                    for (int nt = 0; nt < 8; nt++) {
                        MMA_F16(acc[mt][nt], a[mt], b0[nt]);
                        MMA_F16(acc[mt][nt], a[mt], b1[nt]);
                    }
            }
        }
        if (it + 1 < kSteps) CP_WAIT0();
        __syncthreads();
    }
}

// ============================================================
// Combined QKV projection. grid = (DIM/BN, MTOT/BM, 3)
// z=0: Q -> rope + split-2 f16;  z=1: K -> rope + single f16;
// z=2: V -> smem-staged transposed split-2 f16
// ============================================================
__global__ __launch_bounds__(GTH, 2)
void qkv_mma_kernel(const f16* __restrict__ xh, const f16* __restrict__ xl,
                    const f16* __restrict__ Wf,
                    f16* __restrict__ Qh, f16* __restrict__ Ql,
                    f16* __restrict__ Kf,
                    f16* __restrict__ Vth, f16* __restrict__ Vtl,
                    const float* __restrict__ Ct, const float* __restrict__ St) {
    const int n0 = blockIdx.x * BN;
    const int m0 = blockIdx.y * BM;
    const int z  = blockIdx.z;
    const size_t nw = (size_t)DIM * DIM;

    float acc[4][8][4];
    gemm2s_core<0>(xh + (size_t)m0 * DIM, DIM,
                   xl + (size_t)m0 * DIM, DIM,
                   Wf + z * nw + (size_t)n0 * DIM, DIM,
                   DIM / BK, acc);

    const int tid = threadIdx.x;
    const int wid = tid >> 5;
    const int lane = tid & 31;
    const int grp = lane >> 2;
    const int tig = lane & 3;
    const int wm = (wid & 1) * 64;
    const int wn = (wid >> 1) * 64;

    if (z != 2) {
#pragma unroll
        for (int mt = 0; mt < 4; mt++)
#pragma unroll
            for (int nt = 0; nt < 8; nt++)
#pragma unroll
                for (int h = 0; h < 2; h++) {
                    int row = m0 + wm + mt * 16 + grp + 8 * h;
                    int colE = n0 + wn + nt * 8 + tig * 2;
                    float e = acc[mt][nt][2 * h];
                    float o = acc[mt][nt][2 * h + 1];
                    int s = row & (SEQ - 1);
                    int j = colE >> 1;
                    float cth = Ct[(size_t)s * HALF_D + j];
                    float sth = St[(size_t)s * HALF_D + j];
                    float re = e * cth - o * sth;
                    float ro = e * sth + o * cth;
                    size_t p = (size_t)row * DIM + colE;
                    if (z == 0) {
                        f16 h1, l1, h2, l2;
                        split_f16(re, h1, l1);
                        split_f16(ro, h2, l2);
                        *(f162*)(Qh + p) = f162{h1, h2};
                        *(f162*)(Ql + p) = f162{l1, l2};
                    } else {
                        *(f162*)(Kf + p) = __floats2half2_rn(re, ro);
                    }
                }
    } else {
        // V: stage fp32 tile in smem [col][row], coalesced f16-split stores
        extern __shared__ f16 smem[];
        float* vbuf = (float*)smem;   // 128 x VSTRIDE floats = 68096 B (fits)
#pragma unroll
        for (int mt = 0; mt < 4; mt++)
#pragma unroll
            for (int nt = 0; nt < 8; nt++)
#pragma unroll
                for (int h = 0; h < 2; h++) {
                    int rowL = wm + mt * 16 + grp + 8 * h;
                    int colL = wn + nt * 8 + tig * 2;
                    vbuf[colL * VSTRIDE + rowL]       = acc[mt][nt][2 * h];
                    vbuf[(colL + 1) * VSTRIDE + rowL] = acc[mt][nt][2 * h + 1];
                }
        __syncthreads();

        const int bq = m0 >> 12;
        const int sbase = m0 & (SEQ - 1);
        const int col = tid;
        const float* srcc = vbuf + col * VSTRIDE;
        size_t gbase = ((size_t)bq * DIM + n0 + col) * SEQ + sbase;
#pragma unroll
        for (int j0 = 0; j0 < 128; j0 += 8) {
            f16 h8[8], l8[8];
#pragma unroll
            for (int j = 0; j < 8; j++) split_f16(srcc[j0 + j], h8[j], l8[j]);
            *(uint4*)(Vth + gbase + j0) = *(uint4*)h8;
            *(uint4*)(Vtl + gbase + j0) = *(uint4*)l8;
        }
    }
}

// ============================================================
// Scores+exp: E = exp((Q K^T)/32) masked causal, fp16 output.
// A = Q split-2 (exact), B = K single. grid = (SEQ/BN, SEQ/BM, BATCH)
// ============================================================
__global__ __launch_bounds__(GTH, 2)
void scores_mma_kernel(const f16* __restrict__ Qh, const f16* __restrict__ Ql,
                       const f16* __restrict__ Kf, f16* __restrict__ Pf) {
    const int n0 = blockIdx.x * BN;
    const int m0 = blockIdx.y * BM;
    if (n0 > m0) return;
    const int b = blockIdx.z;
    const size_t boff = (size_t)b * SEQ * DIM;

    float acc[4][8][4];
    gemm2s_core<0>(Qh + boff + (size_t)m0 * DIM, DIM,
                   Ql + boff + (size_t)m0 * DIM, DIM,
                   Kf + boff + (size_t)n0 * DIM, DIM,
                   DIM / BK, acc);

    const int tid = threadIdx.x;
    const int wid = tid >> 5;
    const int lane = tid & 31;
    const int grp = lane >> 2;
    const int tig = lane & 3;
    const int wm = (wid & 1) * 64;
    const int wn = (wid >> 1) * 64;
    const float scale = 1.0f / 32.0f;

    f16* Pb = Pf + (size_t)b * SEQ * SEQ;
#pragma unroll
    for (int mt = 0; mt < 4; mt++)
#pragma unroll
        for (int nt = 0; nt < 8; nt++)
#pragma unroll
            for (int h = 0; h < 2; h++) {
                int row = m0 + wm + mt * 16 + grp + 8 * h;
                int col = n0 + wn + nt * 8 + tig * 2;
                float e0 = (col     <= row) ? __expf(acc[mt][nt][2 * h]     * scale) : 0.0f;
                float e1 = (col + 1 <= row) ? __expf(acc[mt][nt][2 * h + 1] * scale) : 0.0f;
                *(f162*)(Pb + (size_t)row * SEQ + col) = __floats2half2_rn(e0, e1);
            }
}

// ============================================================
// Deterministic per-row sum of fp16 exp values. Block per row.
// ============================================================
__global__ __launch_bounds__(NTHREADS)
void rowsum_kernel(const f16* __restrict__ Pf, float* __restrict__ rsum) {
    __shared__ float red[NTHREADS / 32];
    const int rowg = blockIdx.x;
    const int b = rowg >> 12;
    const int i = rowg & (SEQ - 1);
    const f16* p = Pf + ((size_t)b * SEQ + i) * SEQ;
    const int bound = (i & ~127) + 128;
    const int tid = threadIdx.x;
    const int lane = tid & 31;
    const int wrp = tid >> 5;

    float sum = 0.0f;
    for (int j = tid * 2; j < bound; j += NTHREADS * 2) {
        float2 v = __half22float2(*(const f162*)(p + j));
        sum += v.x + v.y;
    }
#pragma unroll
    for (int o = 16; o > 0; o >>= 1) sum += __shfl_xor_sync(~0u, sum, o);
    if (lane == 0) red[wrp] = sum;
    __syncthreads();
    if (tid == 0) {
        float s = 0.0f;
#pragma unroll
        for (int w = 0; w < NTHREADS / 32; w++) s += red[w];
        rsum[rowg] = s;
    }
}

// ============================================================
// PV: O = (E @ V) / rowsum, A = P single, B = V split-2.
// grid = (DIM/BN, SEQ/BM, BATCH); heavy m-tiles first.
// ============================================================
__global__ __launch_bounds__(GTH, 2)
void pv_mma_kernel(const f16* __restrict__ Pf,
                   const f16* __restrict__ Vth, const f16* __restrict__ Vtl,
                   const float* __restrict__ rsum, float* __restrict__ O) {
    const int n0 = blockIdx.x * BN;
    const int m0 = (int)(gridDim.y - 1 - blockIdx.y) * BM;
    const int b = blockIdx.z;

    float acc[4][8][4];
    gemm2s_core<1>(Pf + (size_t)b * SEQ * SEQ + (size_t)m0 * SEQ, SEQ,
                   Vth + (size_t)b * DIM * SEQ + (size_t)n0 * SEQ, SEQ,
                   Vtl + (size_t)b * DIM * SEQ + (size_t)n0 * SEQ, SEQ,
                   (m0 + BM) / BK, acc);

    const int tid = threadIdx.x;
    const int wid = tid >> 5;
    const int lane = tid & 31;
    const int grp = lane >> 2;
    const int tig = lane & 3;
    const int wm = (wid & 1) * 64;
    const int wn = (wid >> 1) * 64;

#pragma unroll
    for (int mt = 0; mt < 4; mt++)
#pragma unroll
        for (int nt = 0; nt < 8; nt++)
#pragma unroll
            for (int h = 0; h < 2; h++) {
                int row = m0 + wm + mt * 16 + grp + 8 * h;
                int col = n0 + wn + nt * 8 + tig * 2;
                float inv = 1.0f / rsum[(size_t)b * SEQ + row];
                float2 v;
                v.x = acc[mt][nt][2 * h] * inv;
                v.y = acc[mt][nt][2 * h + 1] * inv;
                *(float2*)(O + ((size_t)b * SEQ + row) * DIM + col) = v;
            }
}

// ============================================================
// Launch
// ============================================================
extern "C" void kernel_launch(void* const* d_in, const int* in_sizes, int n_in,
                              void* d_out, int out_size) {
    const float* x  = (const float*)d_in[0];
    const float* Wq = (const float*)d_in[1];
    const float* Wk = (const float*)d_in[2];
    const float* Wv = (const float*)d_in[3];
    float* out = (float*)d_out;

    f16 *xh, *xl, *Wf, *Qh, *Ql, *Kf, *Vth, *Vtl, *Pf;
    float *Rs, *Cp, *Sp;
    cudaGetSymbolAddress((void**)&xh, g_xh);
    cudaGetSymbolAddress((void**)&xl, g_xl);
    cudaGetSymbolAddress((void**)&Wf, g_Wf);
    cudaGetSymbolAddress((void**)&Qh, g_Qh);
    cudaGetSymbolAddress((void**)&Ql, g_Ql);
    cudaGetSymbolAddress((void**)&Kf, g_Kf);
    cudaGetSymbolAddress((void**)&Vth, g_Vth);
    cudaGetSymbolAddress((void**)&Vtl, g_Vtl);
    cudaGetSymbolAddress((void**)&Pf, g_Pf);
    cudaGetSymbolAddress((void**)&Rs, g_rsum);
    cudaGetSymbolAddress((void**)&Cp, g_cos);
    cudaGetSymbolAddress((void**)&Sp, g_sin);

    cudaFuncSetAttribute(qkv_mma_kernel,    cudaFuncAttributeMaxDynamicSharedMemorySize, SMEM_BYTES);
    cudaFuncSetAttribute(scores_mma_kernel, cudaFuncAttributeMaxDynamicSharedMemorySize, SMEM_BYTES);
    cudaFuncSetAttribute(pv_mma_kernel,     cudaFuncAttributeMaxDynamicSharedMemorySize, SMEM_BYTES);

    // 1) trig tables
    {
        int total = SEQ * HALF_D;
        trig_table_kernel<<<(total + 255) / 256, 256>>>(Cp, Sp);
    }
    // 2) split x into f16 hi/lo
    {
        int nx = MTOT * DIM;
        split_x_kernel<<<(nx + 255) / 256, 256>>>(x, xh, xl, nx);
    }
    // 3) convert all weights to f16 (one launch)
    {
        int n3 = 3 * DIM * DIM;
        conv_w3_kernel<<<(n3 + 255) / 256, 256>>>(Wq, Wk, Wv, Wf);
    }

    // 4) QKV projections (single launch, grid.z selects Q/K/V)
    {
        dim3 grid(DIM / BN, MTOT / BM, 3);   // (8, 128, 3)
        qkv_mma_kernel<<<grid, GTH, SMEM_BYTES>>>(xh, xl, Wf,
                                                  Qh, Ql, Kf, Vth, Vtl,
                                                  Cp, Sp);
    }
    // 5) scores + exp + causal mask (fp16 output)
    {
        dim3 grid(SEQ / BN, SEQ / BM, BATCH);
        scores_mma_kernel<<<grid, GTH, SMEM_BYTES>>>(Qh, Ql, Kf, Pf);
    }
    // 6) deterministic row sums
    rowsum_kernel<<<BATCH * SEQ, NTHREADS>>>(Pf, Rs);

    // 7) O = (E @ V) / rowsum
    {
        dim3 grid(DIM / BN, SEQ / BM, BATCH);
        pv_mma_kernel<<<grid, GTH, SMEM_BYTES>>>(Pf, Vth, Vtl, Rs, out);
    }
}

// round 17
// speedup vs baseline: 1.5534x; 1.0834x over previous
#include <cuda_runtime.h>
#include <cuda_fp16.h>
#include <math.h>
#include <stdint.h>

typedef __half f16;
typedef __half2 f162;

// Problem constants
#define BATCH 4
#define SEQ   4096
#define DIM   1024
#define MTOT  (BATCH * SEQ)     // 16384
#define HALF_D (DIM / 2)        // 512

// GEMM tiling: 128x128 CTA tile, 4 warps of 64x64, BK=64
#define BM 128
#define BN 128
#define BK 64
#define GTH 128                         // gemm block threads (4 warps)
#define NTHREADS 256                    // helper-kernel block size
#define SKB 72                          // padded smem row stride (f16) = 144 B
#define BUFB (BM * SKB)                 // 9216 f16 per operand buffer
#define VSTRIDE 133                     // fp32 stage buffer column stride
#define SMEM_BYTES (2 * 3 * BUFB * 2)   // 2 stages x 3 operand slots = 110592 B

// -------- device scratch (no cudaMalloc allowed) --------
__device__ f16  g_xh[(size_t)MTOT * DIM];
__device__ f16  g_xl[(size_t)MTOT * DIM];
__device__ f16  g_Wf[(size_t)3 * DIM * DIM];   // Wq,Wk,Wv single f16
__device__ f16  g_Qf[(size_t)MTOT * DIM];      // Q single f16
__device__ f16  g_Kf[(size_t)MTOT * DIM];      // K single f16
__device__ f16  g_Vth[(size_t)MTOT * DIM];     // fp16 split V^T [b][dim][seq]
__device__ f16  g_Vtl[(size_t)MTOT * DIM];
__device__ f16  g_Pf[(size_t)BATCH * SEQ * SEQ];   // unnormalized exp(scores)
__device__ float g_cos[(size_t)SEQ * HALF_D];
__device__ float g_sin[(size_t)SEQ * HALF_D];

// ============================================================
// helpers
// ============================================================
__device__ __forceinline__ void split_f16(float x, f16& hi, f16& lo) {
    hi = __float2half_rn(x);
    lo = __float2half_rn(x - __half2float(hi));
}

#define MMA_F16(D, A, B)                                                    \
    asm volatile(                                                           \
        "mma.sync.aligned.m16n8k16.row.col.f32.f16.f16.f32 "                \
        "{%0,%1,%2,%3}, {%4,%5,%6,%7}, {%8,%9}, {%0,%1,%2,%3};"             \
        : "+f"((D)[0]), "+f"((D)[1]), "+f"((D)[2]), "+f"((D)[3])            \
        : "r"((A)[0]), "r"((A)[1]), "r"((A)[2]), "r"((A)[3]),               \
          "r"((B)[0]), "r"((B)[1]))

#define LDSM_X4(R, addr)                                                    \
    asm volatile(                                                           \
        "ldmatrix.sync.aligned.m8n8.x4.shared.b16 {%0,%1,%2,%3}, [%4];"     \
        : "=r"((R)[0]), "=r"((R)[1]), "=r"((R)[2]), "=r"((R)[3])            \
        : "r"(addr))

#define CP_ASYNC16(dst, src)                                                \
    asm volatile("cp.async.cg.shared.global [%0], [%1], 16;"                \
                 :: "r"(dst), "l"(src))
#define CP_COMMIT() asm volatile("cp.async.commit_group;")
#define CP_WAIT0()  asm volatile("cp.async.wait_group 0;")

// ============================================================
// RoPE cos/sin table (double precision generation)
// ============================================================
__global__ void trig_table_kernel(float* ct, float* st) {
    int idx = blockIdx.x * blockDim.x + threadIdx.x;
    if (idx >= SEQ * HALF_D) return;
    int s = idx / HALF_D;
    int j = idx % HALF_D;
    double inv = exp(-((double)(2 * j) / (double)DIM) * 9.210340371976184);
    double ang = (double)s * inv;
    double sv, cv;
    sincos(ang, &sv, &cv);
    ct[idx] = (float)cv;
    st[idx] = (float)sv;
}

// ============================================================
// Split fp32 x into f16 hi/lo (exact 2-term representation)
// ============================================================
__global__ void split_x_kernel(const float* __restrict__ src,
                               f16* __restrict__ hi, f16* __restrict__ lo,
                               int n) {
    int i = blockIdx.x * blockDim.x + threadIdx.x;
    if (i >= n) return;
    f16 h, l;
    split_f16(src[i], h, l);
    hi[i] = h;
    lo[i] = l;
}

// Convert three weight matrices to single f16 in one launch
__global__ void conv_w3_kernel(const float* __restrict__ Wq,
                               const float* __restrict__ Wk,
                               const float* __restrict__ Wv,
                               f16* __restrict__ Wf) {
    const int nw = DIM * DIM;
    int i = blockIdx.x * blockDim.x + threadIdx.x;
    if (i >= 3 * nw) return;
    const float* src = (i < nw) ? Wq : (i < 2 * nw) ? Wk : Wv;
    float v = src[i >= 2 * nw ? i - 2 * nw : (i >= nw ? i - nw : i)];
    Wf[i] = __float2half_rn(v);
}

// ============================================================
// Unified fp16 GEMM core, BK=64, 4 warps x (64x64).
// MODE 0 (A split, 2 terms):  acc += T0·T2 + T1·T2
// MODE 1 (B split, 2 terms):  acc += T0·T1 + T0·T2, and accumulate
//         per-row sums of the A operand into rs[mt][h] (for PV norm).
// MODE 2 (single, 1 term):    acc += T0·T1
// Callers pass pointers already offset to their m0/n0 rows.
// ============================================================
template <int MODE>
__device__ __forceinline__ void gemm_core(
    const f16* __restrict__ S0, int ld0,
    const f16* __restrict__ S1, int ld1,
    const f16* __restrict__ S2, int ld2,
    int kSteps, float acc[4][8][4], float rs[4][2]) {
    extern __shared__ f16 smem[];
    const int tid = threadIdx.x;
    const int wid = tid >> 5;
    const int lane = tid & 31;
    const int wm = (wid & 1) * 64;
    const int wn = (wid >> 1) * 64;
    const int NOPS = (MODE == 2) ? 2 : 3;

    const uint32_t a_row  = lane & 15;
    const uint32_t a_koff = (uint32_t)((lane >> 4) << 3);
    const uint32_t b_row  = (uint32_t)((lane & 7) + ((lane >> 4) << 3));
    const uint32_t b_koff = (uint32_t)(((lane >> 3) & 1) << 3);

    uint32_t smem_u32 = (uint32_t)__cvta_generic_to_shared(smem);

#pragma unroll
    for (int mt = 0; mt < 4; mt++)
#pragma unroll
        for (int nt = 0; nt < 8; nt++)
#pragma unroll
            for (int c = 0; c < 4; c++) acc[mt][nt][c] = 0.0f;

    const f16* srcs[3] = {S0, S1, S2};
    const int ldsz[3] = {ld0, ld1, ld2};

    auto load_chunk = [&](int stage, int k0) {
#pragma unroll
        for (int i = 0; i < NOPS * 8; i++) {
            const int op = i >> 3;
            const int q = tid + GTH * (i & 7);       // 0..1023 per operand
            const int r = q >> 3;                    // row 0..127
            const int c = (q & 7) * 8;               // col 0,8,...,56
            uint32_t dst = smem_u32 +
                (uint32_t)(((stage * 3 + op) * BUFB + r * SKB + c) * 2);
            const f16* src = srcs[op] + (size_t)r * ldsz[op] + k0 + c;
            CP_ASYNC16(dst, src);
        }
        CP_COMMIT();
    };

    load_chunk(0, 0);
    CP_WAIT0();
    __syncthreads();

    for (int it = 0; it < kSteps; it++) {
        int s = it & 1;
        if (it + 1 < kSteps) load_chunk((it + 1) & 1, (it + 1) * BK);

        const uint32_t st0 = smem_u32 + (uint32_t)((s * 3 + 0) * BUFB * 2);
        const uint32_t st1 = smem_u32 + (uint32_t)((s * 3 + 1) * BUFB * 2);
        const uint32_t st2 = smem_u32 + (uint32_t)((s * 3 + 2) * BUFB * 2);

#pragma unroll
        for (int kc = 0; kc < 4; kc++) {          // four k16 chunks per BK=64
            const uint32_t kbase = (uint32_t)(kc * 16);
            if (MODE == 0) {
                uint32_t a0[4][4], a1[4][4], b[8][2];
#pragma unroll
                for (int mt = 0; mt < 4; mt++) {
                    uint32_t ra = (uint32_t)(((wm + mt * 16 + a_row) * SKB + kbase + a_koff) * 2);
                    LDSM_X4(a0[mt], st0 + ra);
                    LDSM_X4(a1[mt], st1 + ra);
                }
#pragma unroll
                for (int p = 0; p < 4; p++) {
                    uint32_t rb = (uint32_t)(((wn + p * 16 + b_row) * SKB + kbase + b_koff) * 2);
                    uint32_t t[4];
                    LDSM_X4(t, st2 + rb);
                    b[2 * p][0] = t[0]; b[2 * p][1] = t[1];
                    b[2 * p + 1][0] = t[2]; b[2 * p + 1][1] = t[3];
                }
#pragma unroll
                for (int mt = 0; mt < 4; mt++)
#pragma unroll
                    for (int nt = 0; nt < 8; nt++) {
                        MMA_F16(acc[mt][nt], a0[mt], b[nt]);
                        MMA_F16(acc[mt][nt], a1[mt], b[nt]);
                    }
            } else if (MODE == 1) {
                uint32_t a[4][4], b0[8][2], b1[8][2];
#pragma unroll
                for (int mt = 0; mt < 4; mt++) {
                    uint32_t ra = (uint32_t)(((wm + mt * 16 + a_row) * SKB + kbase + a_koff) * 2);
                    LDSM_X4(a[mt], st0 + ra);
                }
                // per-row sums of A (P operand): regs 0,2 = row grp; 1,3 = row grp+8
#pragma unroll
                for (int mt = 0; mt < 4; mt++) {
                    float2 q0 = __half22float2(*(f162*)&a[mt][0]);
                    float2 q1 = __half22float2(*(f162*)&a[mt][1]);
                    float2 q2 = __half22float2(*(f162*)&a[mt][2]);
                    float2 q3 = __half22float2(*(f162*)&a[mt][3]);
                    rs[mt][0] += (q0.x + q0.y) + (q2.x + q2.y);
                    rs[mt][1] += (q1.x + q1.y) + (q3.x + q3.y);
                }
#pragma unroll
                for (int p = 0; p < 4; p++) {
                    uint32_t rb = (uint32_t)(((wn + p * 16 + b_row) * SKB + kbase + b_koff) * 2);
                    uint32_t t[4];
                    LDSM_X4(t, st1 + rb);
                    b0[2 * p][0] = t[0]; b0[2 * p][1] = t[1];
                    b0[2 * p + 1][0] = t[2]; b0[2 * p + 1][1] = t[3];
                    LDSM_X4(t, st2 + rb);
                    b1[2 * p][0] = t[0]; b1[2 * p][1] = t[1];
                    b1[2 * p + 1][0] = t[2]; b1[2 * p + 1][1] = t[3];
                }
#pragma unroll
                for (int mt = 0; mt < 4; mt++)
#pragma unroll
                    for (int nt = 0; nt < 8; nt++) {
                        MMA_F16(acc[mt][nt], a[mt], b0[nt]);
                        MMA_F16(acc[mt][nt], a[mt], b1[nt]);
                    }
            } else {   // MODE 2: single-term
                uint32_t a[4][4], b[8][2];
#pragma unroll
                for (int mt = 0; mt < 4; mt++) {
                    uint32_t ra = (uint32_t)(((wm + mt * 16 + a_row) * SKB + kbase + a_koff) * 2);
                    LDSM_X4(a[mt], st0 + ra);
                }
#pragma unroll
                for (int p = 0; p < 4; p++) {
                    uint32_t rb = (uint32_t)(((wn + p * 16 + b_row) * SKB + kbase + b_koff) * 2);
                    uint32_t t[4];
                    LDSM_X4(t, st1 + rb);
                    b[2 * p][0] = t[0]; b[2 * p][1] = t[1];
                    b[2 * p + 1][0] = t[2]; b[2 * p + 1][1] = t[3];
                }
#pragma unroll
                for (int mt = 0; mt < 4; mt++)
#pragma unroll
                    for (int nt = 0; nt < 8; nt++)
                        MMA_F16(acc[mt][nt], a[mt], b[nt]);
            }
        }
        if (it + 1 < kSteps) CP_WAIT0();
        __syncthreads();
    }
}

// ============================================================
// Combined QKV projection. grid = (DIM/BN, MTOT/BM, 3)
// z=0: Q -> rope + single f16;  z=1: K -> rope + single f16;
// z=2: V -> smem-staged transposed split-2 f16
// ============================================================
__global__ __launch_bounds__(GTH, 2)
void qkv_mma_kernel(const f16* __restrict__ xh, const f16* __restrict__ xl,
                    const f16* __restrict__ Wf,
                    f16* __restrict__ Qf, f16* __restrict__ Kf,
                    f16* __restrict__ Vth, f16* __restrict__ Vtl,
                    const float* __restrict__ Ct, const float* __restrict__ St) {
    const int n0 = blockIdx.x * BN;
    const int m0 = blockIdx.y * BM;
    const int z  = blockIdx.z;
    const size_t nw = (size_t)DIM * DIM;

    float acc[4][8][4];
    float rs_unused[4][2];
    gemm_core<0>(xh + (size_t)m0 * DIM, DIM,
                 xl + (size_t)m0 * DIM, DIM,
                 Wf + z * nw + (size_t)n0 * DIM, DIM,
                 DIM / BK, acc, rs_unused);

    const int tid = threadIdx.x;
    const int wid = tid >> 5;
    const int lane = tid & 31;
    const int grp = lane >> 2;
    const int tig = lane & 3;
    const int wm = (wid & 1) * 64;
    const int wn = (wid >> 1) * 64;

    if (z != 2) {
        f16* Of = (z == 0) ? Qf : Kf;
#pragma unroll
        for (int mt = 0; mt < 4; mt++)
#pragma unroll
            for (int nt = 0; nt < 8; nt++)
#pragma unroll
                for (int h = 0; h < 2; h++) {
                    int row = m0 + wm + mt * 16 + grp + 8 * h;
                    int colE = n0 + wn + nt * 8 + tig * 2;
                    float e = acc[mt][nt][2 * h];
                    float o = acc[mt][nt][2 * h + 1];
                    int s = row & (SEQ - 1);
                    int j = colE >> 1;
                    float cth = Ct[(size_t)s * HALF_D + j];
                    float sth = St[(size_t)s * HALF_D + j];
                    float re = e * cth - o * sth;
                    float ro = e * sth + o * cth;
                    *(f162*)(Of + (size_t)row * DIM + colE) = __floats2half2_rn(re, ro);
                }
    } else {
        // V: stage fp32 tile in smem [col][row], coalesced f16-split stores
        extern __shared__ f16 smem[];
        float* vbuf = (float*)smem;   // 128 x VSTRIDE floats = 68096 B (fits)
#pragma unroll
        for (int mt = 0; mt < 4; mt++)
#pragma unroll
            for (int nt = 0; nt < 8; nt++)
#pragma unroll
                for (int h = 0; h < 2; h++) {
                    int rowL = wm + mt * 16 + grp + 8 * h;
                    int colL = wn + nt * 8 + tig * 2;
                    vbuf[colL * VSTRIDE + rowL]       = acc[mt][nt][2 * h];
                    vbuf[(colL + 1) * VSTRIDE + rowL] = acc[mt][nt][2 * h + 1];
                }
        __syncthreads();

        const int bq = m0 >> 12;
        const int sbase = m0 & (SEQ - 1);
        const int col = tid;
        const float* srcc = vbuf + col * VSTRIDE;
        size_t gbase = ((size_t)bq * DIM + n0 + col) * SEQ + sbase;
#pragma unroll
        for (int j0 = 0; j0 < 128; j0 += 8) {
            f16 h8[8], l8[8];
#pragma unroll
            for (int j = 0; j < 8; j++) split_f16(srcc[j0 + j], h8[j], l8[j]);
            *(uint4*)(Vth + gbase + j0) = *(uint4*)h8;
            *(uint4*)(Vtl + gbase + j0) = *(uint4*)l8;
        }
    }
}

// ============================================================
// Scores+exp: E = exp((Q K^T)/32) masked causal, fp16 output.
// Single-term f16 MMA (Q and K both single). grid = (SEQ/BN, SEQ/BM, BATCH)
// ============================================================
__global__ __launch_bounds__(GTH, 2)
void scores_mma_kernel(const f16* __restrict__ Qf, const f16* __restrict__ Kf,
                       f16* __restrict__ Pf) {
    const int n0 = blockIdx.x * BN;
    const int m0 = blockIdx.y * BM;
    if (n0 > m0) return;
    const int b = blockIdx.z;
    const size_t boff = (size_t)b * SEQ * DIM;

    float acc[4][8][4];
    float rs_unused[4][2];
    gemm_core<2>(Qf + boff + (size_t)m0 * DIM, DIM,
                 Kf + boff + (size_t)n0 * DIM, DIM,
                 Kf + boff + (size_t)n0 * DIM, DIM,
                 DIM / BK, acc, rs_unused);

    const int tid = threadIdx.x;
    const int wid = tid >> 5;
    const int lane = tid & 31;
    const int grp = lane >> 2;
    const int tig = lane & 3;
    const int wm = (wid & 1) * 64;
    const int wn = (wid >> 1) * 64;
    const float scale = 1.0f / 32.0f;

    f16* Pb = Pf + (size_t)b * SEQ * SEQ;
#pragma unroll
    for (int mt = 0; mt < 4; mt++)
#pragma unroll
        for (int nt = 0; nt < 8; nt++)
#pragma unroll
            for (int h = 0; h < 2; h++) {
                int row = m0 + wm + mt * 16 + grp + 8 * h;
                int col = n0 + wn + nt * 8 + tig * 2;
                float e0 = (col     <= row) ? __expf(acc[mt][nt][2 * h]     * scale) : 0.0f;
                float e1 = (col + 1 <= row) ? __expf(acc[mt][nt][2 * h + 1] * scale) : 0.0f;
                *(f162*)(Pb + (size_t)row * SEQ + col) = __floats2half2_rn(e0, e1);
            }
}

// ============================================================
// PV: O = (E @ V) / rowsum, A = P single, B = V split-2.
// Row sums computed in-core from the A fragments (no extra pass).
// grid = (DIM/BN, SEQ/BM, BATCH); heavy m-tiles first.
// ============================================================
__global__ __launch_bounds__(GTH, 2)
void pv_mma_kernel(const f16* __restrict__ Pf,
                   const f16* __restrict__ Vth, const f16* __restrict__ Vtl,
                   float* __restrict__ O) {
    const int n0 = blockIdx.x * BN;
    const int m0 = (int)(gridDim.y - 1 - blockIdx.y) * BM;
    const int b = blockIdx.z;

    float acc[4][8][4];
    float rs[4][2];
#pragma unroll
    for (int mt = 0; mt < 4; mt++) { rs[mt][0] = 0.0f; rs[mt][1] = 0.0f; }

    gemm_core<1>(Pf + (size_t)b * SEQ * SEQ + (size_t)m0 * SEQ, SEQ,
                 Vth + (size_t)b * DIM * SEQ + (size_t)n0 * SEQ, SEQ,
                 Vtl + (size_t)b * DIM * SEQ + (size_t)n0 * SEQ, SEQ,
                 (m0 + BM) / BK, acc, rs);

    // reduce row sums across the k-slices (tig lanes: xor 1, 2)
#pragma unroll
    for (int mt = 0; mt < 4; mt++)
#pragma unroll
        for (int h = 0; h < 2; h++) {
            float v = rs[mt][h];
            v += __shfl_xor_sync(~0u, v, 1);
            v += __shfl_xor_sync(~0u, v, 2);
            rs[mt][h] = v;
        }

    const int tid = threadIdx.x;
    const int wid = tid >> 5;
    const int lane = tid & 31;
    const int grp = lane >> 2;
    const int tig = lane & 3;
    const int wm = (wid & 1) * 64;
    const int wn = (wid >> 1) * 64;

#pragma unroll
    for (int mt = 0; mt < 4; mt++)
#pragma unroll
        for (int nt = 0; nt < 8; nt++)
#pragma unroll
            for (int h = 0; h < 2; h++) {
                int row = m0 + wm + mt * 16 + grp + 8 * h;
                int col = n0 + wn + nt * 8 + tig * 2;
                float inv = 1.0f / rs[mt][h];
                float2 v;
                v.x = acc[mt][nt][2 * h] * inv;
                v.y = acc[mt][nt][2 * h + 1] * inv;
                *(float2*)(O + ((size_t)b * SEQ + row) * DIM + col) = v;
            }
}

// ============================================================
// Launch
// ============================================================
extern "C" void kernel_launch(void* const* d_in, const int* in_sizes, int n_in,
                              void* d_out, int out_size) {
    const float* x  = (const float*)d_in[0];
    const float* Wq = (const float*)d_in[1];
    const float* Wk = (const float*)d_in[2];
    const float* Wv = (const float*)d_in[3];
    float* out = (float*)d_out;

    f16 *xh, *xl, *Wf, *Qf, *Kf, *Vth, *Vtl, *Pf;
    float *Cp, *Sp;
    cudaGetSymbolAddress((void**)&xh, g_xh);
    cudaGetSymbolAddress((void**)&xl, g_xl);
    cudaGetSymbolAddress((void**)&Wf, g_Wf);
    cudaGetSymbolAddress((void**)&Qf, g_Qf);
    cudaGetSymbolAddress((void**)&Kf, g_Kf);
    cudaGetSymbolAddress((void**)&Vth, g_Vth);
    cudaGetSymbolAddress((void**)&Vtl, g_Vtl);
    cudaGetSymbolAddress((void**)&Pf, g_Pf);
    cudaGetSymbolAddress((void**)&Cp, g_cos);
    cudaGetSymbolAddress((void**)&Sp, g_sin);

    cudaFuncSetAttribute(qkv_mma_kernel,    cudaFuncAttributeMaxDynamicSharedMemorySize, SMEM_BYTES);
    cudaFuncSetAttribute(scores_mma_kernel, cudaFuncAttributeMaxDynamicSharedMemorySize, SMEM_BYTES);
    cudaFuncSetAttribute(pv_mma_kernel,     cudaFuncAttributeMaxDynamicSharedMemorySize, SMEM_BYTES);

    // 1) trig tables
    {
        int total = SEQ * HALF_D;
        trig_table_kernel<<<(total + 255) / 256, 256>>>(Cp, Sp);
    }
    // 2) split x into f16 hi/lo
    {
        int nx = MTOT * DIM;
        split_x_kernel<<<(nx + 255) / 256, 256>>>(x, xh, xl, nx);
    }
    // 3) convert all weights to f16 (one launch)
    {
        int n3 = 3 * DIM * DIM;
        conv_w3_kernel<<<(n3 + 255) / 256, 256>>>(Wq, Wk, Wv, Wf);
    }

    // 4) QKV projections (single launch, grid.z selects Q/K/V)
    {
        dim3 grid(DIM / BN, MTOT / BM, 3);   // (8, 128, 3)
        qkv_mma_kernel<<<grid, GTH, SMEM_BYTES>>>(xh, xl, Wf,
                                                  Qf, Kf, Vth, Vtl,
                                                  Cp, Sp);
    }
    // 5) scores + exp + causal mask (fp16 output, single-term MMA)
    {
        dim3 grid(SEQ / BN, SEQ / BM, BATCH);
        scores_mma_kernel<<<grid, GTH, SMEM_BYTES>>>(Qf, Kf, Pf);
    }
    // 6) O = (E @ V) / rowsum (rowsum fused into PV)
    {
        dim3 grid(DIM / BN, SEQ / BM, BATCH);
        pv_mma_kernel<<<grid, GTH, SMEM_BYTES>>>(Pf, Vth, Vtl, out);
    }
}